// round 10
// baseline (speedup 1.0000x reference)
#include <cuda_runtime.h>
#include <cuda_bf16.h>
#include <cstdint>

#define Bb   2
#define Tt   2048
#define DM   1024
#define Hh   16
#define Dd   64
#define BT   4096          // B*T
#define QAB  1024          // H*D
#define CH   64            // chunk length
#define NC   32            // T / CH

// ---------------- scratch (device globals; no allocs allowed) ----------------
__device__ float g_q  [BT * QAB];
__device__ float g_a  [BT * QAB];
__device__ float g_b  [BT * QAB];
__device__ float g_aex[BT * QAB];
__device__ float g_P  [Bb * Hh * NC * Dd * Dd];   // stored TRANSPOSED: [e][d]
__device__ float g_M  [Bb * Hh * NC * Dd * Dd];   // exclusive scan of P^T = M^T
__device__ float g_cs [Bb * QAB * NC];

// bf16 split operands
__device__ __nv_bfloat16 g_xh[BT * DM];
__device__ __nv_bfloat16 g_xl[BT * DM];
__device__ __nv_bfloat16 g_oh[BT * QAB];
__device__ __nv_bfloat16 g_ol[BT * QAB];
__device__ __nv_bfloat16 g_wh[4u << 20];   // 4 weights, each [N=1024][K=1024] (transposed)
__device__ __nv_bfloat16 g_wl[4u << 20];

// ================= helpers ==================
__device__ __forceinline__ uint32_t smem_u32(const void* p) {
    uint32_t a;
    asm("{ .reg .u64 t; cvta.to.shared.u64 t, %1; cvt.u32.u64 %0, t; }" : "=r"(a) : "l"(p));
    return a;
}
#define SMEM_SWIZZLE_128B(off) ((off) ^ (((off) >> 3) & 0x70))

__device__ __forceinline__ void cp16(uint32_t dst, const void* src) {
    asm volatile("cp.async.cg.shared.global [%0], [%1], 16;" :: "r"(dst), "l"(src));
}
#define CP_COMMIT() asm volatile("cp.async.commit_group;" ::: "memory")

__device__ __forceinline__ void ldsm4(uint32_t* r, uint32_t a) {
    asm volatile("ldmatrix.sync.aligned.m8n8.x4.shared.b16 {%0,%1,%2,%3}, [%4];"
                 : "=r"(r[0]), "=r"(r[1]), "=r"(r[2]), "=r"(r[3]) : "r"(a));
}

__device__ __forceinline__ void mma16816(float* c, const uint32_t* a,
                                         uint32_t b0, uint32_t b1) {
    asm volatile(
        "mma.sync.aligned.m16n8k16.row.col.f32.bf16.bf16.f32 "
        "{%0,%1,%2,%3}, {%4,%5,%6,%7}, {%8,%9}, {%0,%1,%2,%3};"
        : "+f"(c[0]), "+f"(c[1]), "+f"(c[2]), "+f"(c[3])
        : "r"(a[0]), "r"(a[1]), "r"(a[2]), "r"(a[3]), "r"(b0), "r"(b1));
}

// pack two fp32 into bf16x2 hi/lo splits
__device__ __forceinline__ void split2(float x, float y, uint32_t& hi, uint32_t& lo) {
    __nv_bfloat16 hx = __float2bfloat16(x), hy = __float2bfloat16(y);
    float rx = x - __bfloat162float(hx), ry = y - __bfloat162float(hy);
    __nv_bfloat16 lx = __float2bfloat16(rx), ly = __float2bfloat16(ry);
    hi = ((uint32_t)__bfloat16_as_ushort(hy) << 16) | (uint32_t)__bfloat16_as_ushort(hx);
    lo = ((uint32_t)__bfloat16_as_ushort(ly) << 16) | (uint32_t)__bfloat16_as_ushort(lx);
}

// ================= HMMA GEMM: C = A(hi+lo bf16) @ W^T (W stored [N,K]) ======
// CTA tile 128x128, BK=64, 3-stage cp.async ring, 256 threads.
// Warp grid 4(M) x 2(N), warp tile 32x64. Fragment DOUBLE-BUFFERING over the
// four k16 steps: ldsm for step t+1 issues before the MMAs of step t, hiding
// the 29-cyc LDS latency inside each warp (ILP instead of TLP; 256 regs avail).
#define GM_STAGE 65536                 // Ah 16K | Al 16K | Bh 16K | Bl 16K
#define GM_SMEM  (3 * GM_STAGE)

__device__ __forceinline__ void gemm_mma(const __nv_bfloat16* __restrict__ Ah,
                                         const __nv_bfloat16* __restrict__ Al,
                                         const __nv_bfloat16* __restrict__ Bh,
                                         const __nv_bfloat16* __restrict__ Bl,
                                         float* __restrict__ C, int ldc,
                                         int bm, int bn,
                                         const float* __restrict__ gamma,
                                         const float* __restrict__ beta) {
    extern __shared__ char smem[];
    const uint32_t sb = smem_u32(smem);
    const int tid = threadIdx.x, wid = tid >> 5, lane = tid & 31;
    const int m0 = (wid >> 1) * 32;     // warp row base in tile
    const int n0 = (wid & 1) * 64;      // warp col base in tile

    float acc[2][8][4];
#pragma unroll
    for (int i = 0; i < 2; i++)
#pragma unroll
        for (int j = 0; j < 8; j++)
#pragma unroll
            for (int k = 0; k < 4; k++) acc[i][j][k] = 0.f;

    auto load_stage = [&](int st, int k0) {
        uint32_t base = sb + st * GM_STAGE;
#pragma unroll
        for (int tile = 0; tile < 4; tile++) {
            const __nv_bfloat16* src = tile == 0 ? Ah : tile == 1 ? Al
                                     : tile == 2 ? Bh : Bl;
            const int rb = (tile < 2) ? bm : bn;
#pragma unroll
            for (int s = tid; s < 1024; s += 256) {
                int row = s >> 3, ks = s & 7;
                uint32_t dst = base + tile * 16384 +
                               SMEM_SWIZZLE_128B((uint32_t)(row * 128 + ks * 16));
                cp16(dst, src + (size_t)(rb + row) * 1024 + k0 + ks * 8);
            }
        }
        CP_COMMIT();
    };

    const int ar  = lane & 15, ac16 = lane >> 4;             // A 16x16
    const int bsub = lane >> 3, br8 = lane & 7;              // B 16x16
    const int brow = ((bsub & 1) ? 8 : 0) + br8;
    const int bcsel = (bsub >> 1) ? 16 : 0;

    // double-buffered fragments (buf = t&1)
    uint32_t ahf[2][2][4], alf[2][2][4], bhf[2][4][4], blf[2][4][4];

    load_stage(0, 0);       // chunk 0 -> buf 0
    load_stage(1, 64);      // chunk 1 -> buf 1
    for (int i = 0; i < 16; i++) {
        asm volatile("cp.async.wait_group 1;" ::: "memory");   // chunk-i groups done
        __syncthreads();                                       // buf i%3 valid CTA-wide

        const uint32_t ahb = sb + (i % 3) * GM_STAGE;
        const uint32_t alb = ahb + 16384, bhb = ahb + 32768, blb = ahb + 49152;

        // frag loader for k16 step t into reg buffer bf
        auto load_frags = [&](int t, int bf) {
#pragma unroll
            for (int mi = 0; mi < 2; mi++) {
                uint32_t aoff = SMEM_SWIZZLE_128B(
                    (uint32_t)((m0 + mi * 16 + ar) * 128 + t * 32 + ac16 * 16));
                ldsm4(ahf[bf][mi], ahb + aoff);
                ldsm4(alf[bf][mi], alb + aoff);
            }
#pragma unroll
            for (int g = 0; g < 4; g++) {
                uint32_t off = SMEM_SWIZZLE_128B(
                    (uint32_t)((n0 + g * 16 + brow) * 128 + t * 32 + bcsel));
                ldsm4(bhf[bf][g], bhb + off);
                ldsm4(blf[bf][g], blb + off);
            }
        };

        load_frags(0, 0);                                  // prime step 0
        // prefetch chunk i+2 into buf (i+2)%3 (overlaps with MMA below)
        if (i < 14) load_stage((i + 2) % 3, (i + 2) * 64);
        else CP_COMMIT();                  // empty group keeps wait_group counts aligned

#pragma unroll
        for (int t = 0; t < 4; t++) {
            const int cb = t & 1;
            if (t < 3) load_frags(t + 1, cb ^ 1);          // hide LDS latency behind MMAs
#pragma unroll
            for (int mi = 0; mi < 2; mi++)
#pragma unroll
                for (int nj = 0; nj < 8; nj++) {
                    int g = nj >> 1, s2 = nj & 1;
                    mma16816(acc[mi][nj], ahf[cb][mi], bhf[cb][g][s2], bhf[cb][g][s2 + 2]);
                    mma16816(acc[mi][nj], ahf[cb][mi], blf[cb][g][s2], blf[cb][g][s2 + 2]);
                    mma16816(acc[mi][nj], alf[cb][mi], bhf[cb][g][s2], bhf[cb][g][s2 + 2]);
                }
        }
    }

    const int r4 = lane >> 2, c2 = (lane & 3) * 2;

    // -------- fused per-head LayerNorm (head == warp's 64-col span) --------
    if (gamma) {
        float gv[16], bv[16];
#pragma unroll
        for (int nj = 0; nj < 8; nj++)
#pragma unroll
            for (int t = 0; t < 2; t++) {
                int d = nj * 8 + c2 + t;
                gv[nj * 2 + t] = __ldg(gamma + d);
                bv[nj * 2 + t] = __ldg(beta + d);
            }
#pragma unroll
        for (int mi = 0; mi < 2; mi++) {
            float s0 = 0.f, q0 = 0.f, s1 = 0.f, q1 = 0.f;
#pragma unroll
            for (int nj = 0; nj < 8; nj++) {
                float v0 = acc[mi][nj][0], v1 = acc[mi][nj][1];
                float v2 = acc[mi][nj][2], v3 = acc[mi][nj][3];
                s0 += v0 + v1; q0 += v0 * v0 + v1 * v1;
                s1 += v2 + v3; q1 += v2 * v2 + v3 * v3;
            }
#pragma unroll
            for (int o = 1; o <= 2; o <<= 1) {
                s0 += __shfl_xor_sync(0xFFFFFFFFu, s0, o);
                q0 += __shfl_xor_sync(0xFFFFFFFFu, q0, o);
                s1 += __shfl_xor_sync(0xFFFFFFFFu, s1, o);
                q1 += __shfl_xor_sync(0xFFFFFFFFu, q1, o);
            }
            float m0s = s0 * (1.f / 64.f);
            float r0 = rsqrtf(q0 * (1.f / 64.f) - m0s * m0s + 1e-5f);
            float m1s = s1 * (1.f / 64.f);
            float r1 = rsqrtf(q1 * (1.f / 64.f) - m1s * m1s + 1e-5f);
#pragma unroll
            for (int nj = 0; nj < 8; nj++) {
                acc[mi][nj][0] = (acc[mi][nj][0] - m0s) * r0 * gv[nj * 2]     + bv[nj * 2];
                acc[mi][nj][1] = (acc[mi][nj][1] - m0s) * r0 * gv[nj * 2 + 1] + bv[nj * 2 + 1];
                acc[mi][nj][2] = (acc[mi][nj][2] - m1s) * r1 * gv[nj * 2]     + bv[nj * 2];
                acc[mi][nj][3] = (acc[mi][nj][3] - m1s) * r1 * gv[nj * 2 + 1] + bv[nj * 2 + 1];
            }
        }
    }

    // epilogue: c frag -> gmem fp32
#pragma unroll
    for (int mi = 0; mi < 2; mi++)
#pragma unroll
        for (int nj = 0; nj < 8; nj++) {
            int m = bm + m0 + mi * 16 + r4;
            int n = bn + n0 + nj * 8 + c2;
            float2 v0 = make_float2(acc[mi][nj][0], acc[mi][nj][1]);
            float2 v1 = make_float2(acc[mi][nj][2], acc[mi][nj][3]);
            *reinterpret_cast<float2*>(C + (size_t)m * ldc + n) = v0;
            *reinterpret_cast<float2*>(C + (size_t)(m + 8) * ldc + n) = v1;
        }
}

__global__ __launch_bounds__(256, 1) void proj_tc_kernel(const float* __restrict__ qg,
                                                         const float* __restrict__ qb,
                                                         const float* __restrict__ ag,
                                                         const float* __restrict__ ab,
                                                         const float* __restrict__ bg,
                                                         const float* __restrict__ bbv) {
    const int w = blockIdx.x >> 3, nt = blockIdx.x & 7, bm = blockIdx.y * 128;
    const __nv_bfloat16* Bh = g_wh + ((size_t)w << 20);
    const __nv_bfloat16* Bl = g_wl + ((size_t)w << 20);
    float* C;
    const float* gm;
    const float* bt;
    if (w == 0)      { C = g_q; gm = qg; bt = qb; }
    else if (w == 1) { C = g_a; gm = ag; bt = ab; }
    else             { C = g_b; gm = bg; bt = bbv; }
    gemm_mma(g_xh, g_xl, Bh, Bl, C, QAB, bm, nt * 128, gm, bt);
}

__global__ __launch_bounds__(256, 1) void out_tc_kernel(float* __restrict__ out) {
    const int nt = blockIdx.x, bm = blockIdx.y * 128;
    const __nv_bfloat16* Bh = g_wh + ((size_t)3 << 20);
    const __nv_bfloat16* Bl = g_wl + ((size_t)3 << 20);
    gemm_mma(g_oh, g_ol, Bh, Bl, out, DM, bm, nt * 128, nullptr, nullptr);
}

// ---------------- split fp32 x -> hi/lo bf16 ----------------
__global__ __launch_bounds__(256) void split_kernel(const float* __restrict__ in) {
    size_t i = ((size_t)blockIdx.x * 256 + threadIdx.x) * 4;
    float4 v = *reinterpret_cast<const float4*>(in + i);
    float vv[4] = {v.x, v.y, v.z, v.w};
#pragma unroll
    for (int j = 0; j < 4; j++) {
        __nv_bfloat16 h = __float2bfloat16(vv[j]);
        g_xh[i + j] = h;
        g_xl[i + j] = __float2bfloat16(vv[j] - __bfloat162float(h));
    }
}

// weights: fp32 [K=1024, N=1024] -> transposed bf16 hi/lo [N, K]; 2 weights/launch
__global__ __launch_bounds__(256) void wsplit2_kernel(const float* __restrict__ WA,
                                                      const float* __restrict__ WB,
                                                      int wbase) {
    const float* W = (blockIdx.z == 0) ? WA : WB;
    const int widx = wbase + blockIdx.z;
    __shared__ float t[32][33];
    const int bx = blockIdx.x * 32;   // n
    const int by = blockIdx.y * 32;   // k
    const int tx = threadIdx.x & 31, ty = threadIdx.x >> 5;
#pragma unroll
    for (int r = 0; r < 32; r += 8)
        t[ty + r][tx] = W[(size_t)(by + ty + r) * 1024 + bx + tx];
    __syncthreads();
    __nv_bfloat16* oh = g_wh + ((size_t)widx << 20);
    __nv_bfloat16* ol = g_wl + ((size_t)widx << 20);
#pragma unroll
    for (int r = 0; r < 32; r += 8) {
        float v = t[tx][ty + r];                          // = W[by+tx][bx+ty+r]
        __nv_bfloat16 h = __float2bfloat16(v);
        size_t oi = (size_t)(bx + ty + r) * 1024 + by + tx;
        oh[oi] = h;
        ol[oi] = __float2bfloat16(v - __bfloat162float(h));
    }
}

// ---------------- exclusive cumsum of a along time (two-pass) ----------------
__global__ __launch_bounds__(256) void chunksum_kernel() {
    int gid = blockIdx.x * 256 + threadIdx.x;
    int col = gid % QAB;
    int c   = (gid / QAB) % NC;
    int b   = gid / (QAB * NC);
    const float* p = g_a + (size_t)(b * Tt + c * CH) * QAB + col;
    float s = 0.f;
#pragma unroll 8
    for (int r = 0; r < CH; r++) s += p[(size_t)r * QAB];
    g_cs[(b * NC + c) * QAB + col] = s;
}

__global__ __launch_bounds__(256) void excl_kernel() {
    int gid = blockIdx.x * 256 + threadIdx.x;
    int col = gid % QAB;
    int c   = (gid / QAB) % NC;
    int b   = gid / (QAB * NC);
    float off = 0.f;
    for (int cc = 0; cc < c; cc++) off += g_cs[(b * NC + cc) * QAB + col];
    const float* pa = g_a   + (size_t)(b * Tt + c * CH) * QAB + col;
    float*       pe = g_aex + (size_t)(b * Tt + c * CH) * QAB + col;
    float run = off;
#pragma unroll 8
    for (int r = 0; r < CH; r++) {
        pe[(size_t)r * QAB] = run;
        run += pa[(size_t)r * QAB];
    }
}

// -------- per-chunk outer product, stored transposed: P^T[e][d] = sum_t B[t][e] Aex[t][d]
__global__ __launch_bounds__(256) void chunkP_kernel() {
    int c = blockIdx.x & (NC - 1);
    int h = (blockIdx.x >> 5) & (Hh - 1);
    int b = blockIdx.x >> 9;
    __shared__ float Ax[64][64];
    __shared__ float Bx[64][64];
    int tid = threadIdx.x;
    size_t base = (size_t)(b * Tt + c * CH) * QAB + h * Dd;
    for (int idx = tid; idx < 4096; idx += 256) {
        int t = idx >> 6, d = idx & 63;
        Ax[t][d] = g_aex[base + (size_t)t * QAB + d];
        Bx[t][d] = g_b [base + (size_t)t * QAB + d];
    }
    __syncthreads();
    int dr = (tid >> 4) * 4, ec = (tid & 15) * 4;
    float acc[4][4] = {};
#pragma unroll 4
    for (int t = 0; t < 64; t++) {
        float av[4], bv[4];
#pragma unroll
        for (int i = 0; i < 4; i++) av[i] = Ax[t][dr + i];
#pragma unroll
        for (int j = 0; j < 4; j++) bv[j] = Bx[t][ec + j];
#pragma unroll
        for (int i = 0; i < 4; i++)
#pragma unroll
            for (int j = 0; j < 4; j++)
                acc[i][j] = fmaf(av[i], bv[j], acc[i][j]);
    }
    size_t pb = ((size_t)((b * Hh + h) * NC + c)) * 4096;
#pragma unroll
    for (int j = 0; j < 4; j++) {       // transposed store: row e, col d
        float4 v = make_float4(acc[0][j], acc[1][j], acc[2][j], acc[3][j]);
        *reinterpret_cast<float4*>(g_P + pb + (size_t)(ec + j) * 64 + dr) = v;
    }
}

// ---------------- elementwise exclusive scan of P^T over chunks -> M^T -------
__global__ __launch_bounds__(256) void scanM_kernel() {
    int gid = blockIdx.x * 256 + threadIdx.x;
    int de = gid & 4095;
    int bh = gid >> 12;
    size_t base = (size_t)bh * NC * 4096 + de;
    float run = 0.f;
#pragma unroll
    for (int c = 0; c < NC; c++) {
        g_M[base + (size_t)c * 4096] = run;
        run += g_P[base + (size_t)c * 4096];
    }
}

// ---------------- chunk attention via HMMA -----------------------------------
// S = tril(Q Aex^T);  O = Q M^T_rows + S B^T_rows;  output -> g_oh/g_ol (split)
#define OQ_H 0
#define OQ_L 8192
#define OA_H 16384
#define OA_L 24576
#define OB_H 32768
#define OB_L 40960
#define OM_H 49152
#define OM_L 57344
#define ATT_SMEM 65536

__global__ __launch_bounds__(128, 1) void attn_kernel() {
    extern __shared__ char smem[];
    const uint32_t sb = smem_u32(smem);
    int c = blockIdx.x & (NC - 1);
    int h = (blockIdx.x >> 5) & (Hh - 1);
    int b = blockIdx.x >> 9;
    int tid = threadIdx.x, wid = tid >> 5, lane = tid & 31;
    size_t base  = (size_t)(b * Tt + c * CH) * QAB + h * Dd;
    size_t mbase = ((size_t)((b * Hh + h) * NC + c)) * 4096;

    // load + convert to split bf16 smem (SW128 rows of 128B)
    for (int idx = tid; idx < 4096; idx += 128) {
        int t = idx >> 6, d = idx & 63;
        size_t go = base + (size_t)t * QAB + d;
        float q  = g_q[go];
        float a  = g_aex[go];
        float bv = g_b[go];
        float m  = g_M[mbase + idx];                       // row e=t, col d (M^T)
        uint32_t offr = SMEM_SWIZZLE_128B((uint32_t)(t * 128 + d * 2));
        uint32_t offt = SMEM_SWIZZLE_128B((uint32_t)(d * 128 + t * 2));  // B transposed
        __nv_bfloat16 hh, ll;
        hh = __float2bfloat16(q);  ll = __float2bfloat16(q - __bfloat162float(hh));
        *(__nv_bfloat16*)(smem + OQ_H + offr) = hh;
        *(__nv_bfloat16*)(smem + OQ_L + offr) = ll;
        hh = __float2bfloat16(a);  ll = __float2bfloat16(a - __bfloat162float(hh));
        *(__nv_bfloat16*)(smem + OA_H + offr) = hh;
        *(__nv_bfloat16*)(smem + OA_L + offr) = ll;
        hh = __float2bfloat16(bv); ll = __float2bfloat16(bv - __bfloat162float(hh));
        *(__nv_bfloat16*)(smem + OB_H + offt) = hh;
        *(__nv_bfloat16*)(smem + OB_L + offt) = ll;
        hh = __float2bfloat16(m);  ll = __float2bfloat16(m - __bfloat162float(hh));
        *(__nv_bfloat16*)(smem + OM_H + offr) = hh;
        *(__nv_bfloat16*)(smem + OM_L + offr) = ll;
    }
    __syncthreads();

    const int m0 = wid * 16;
    const int ar = lane & 15, ac16 = lane >> 4;
    const int bsub = lane >> 3, br8 = lane & 7;
    const int brow = ((bsub & 1) ? 8 : 0) + br8;
    const int bcsel = (bsub >> 1) ? 16 : 0;
    const int r4 = lane >> 2, c2 = (lane & 3) * 2;

    // ---- gemm1: S = Q @ Aex^T ----
    float sacc[8][4];
#pragma unroll
    for (int j = 0; j < 8; j++)
#pragma unroll
        for (int k = 0; k < 4; k++) sacc[j][k] = 0.f;
#pragma unroll
    for (int t = 0; t < 4; t++) {
        uint32_t qh[4], ql[4], bh_[4][4], bl_[4][4];
        uint32_t aoff = SMEM_SWIZZLE_128B((uint32_t)((m0 + ar) * 128 + t * 32 + ac16 * 16));
        ldsm4(qh, sb + OQ_H + aoff);
        ldsm4(ql, sb + OQ_L + aoff);
#pragma unroll
        for (int g = 0; g < 4; g++) {
            uint32_t boff = SMEM_SWIZZLE_128B((uint32_t)((g * 16 + brow) * 128 + t * 32 + bcsel));
            ldsm4(bh_[g], sb + OA_H + boff);
            ldsm4(bl_[g], sb + OA_L + boff);
        }
#pragma unroll
        for (int nj = 0; nj < 8; nj++) {
            int g = nj >> 1, s2 = nj & 1;
            mma16816(sacc[nj], qh, bh_[g][s2], bh_[g][s2 + 2]);
            mma16816(sacc[nj], qh, bl_[g][s2], bl_[g][s2 + 2]);
            mma16816(sacc[nj], ql, bh_[g][s2], bh_[g][s2 + 2]);
        }
    }

    // causal mask (keep s <= t)
    const int row0 = m0 + r4, row1 = row0 + 8;
#pragma unroll
    for (int nj = 0; nj < 8; nj++) {
        int col = nj * 8 + c2;
        if (col     > row0) sacc[nj][0] = 0.f;
        if (col + 1 > row0) sacc[nj][1] = 0.f;
        if (col     > row1) sacc[nj][2] = 0.f;
        if (col + 1 > row1) sacc[nj][3] = 0.f;
    }

    // S C-frags -> A-frags (hi/lo), pure register repack
    uint32_t sh[4][4], sl[4][4];
#pragma unroll
    for (int j = 0; j < 4; j++) {
        split2(sacc[2 * j][0],     sacc[2 * j][1],     sh[j][0], sl[j][0]);
        split2(sacc[2 * j][2],     sacc[2 * j][3],     sh[j][1], sl[j][1]);
        split2(sacc[2 * j + 1][0], sacc[2 * j + 1][1], sh[j][2], sl[j][2]);
        split2(sacc[2 * j + 1][2], sacc[2 * j + 1][3], sh[j][3], sl[j][3]);
    }

    // ---- gemm2: O = Q @ M^T  (+ gemm3: O += S @ B^T) ----
    float oacc[8][4];
#pragma unroll
    for (int j = 0; j < 8; j++)
#pragma unroll
        for (int k = 0; k < 4; k++) oacc[j][k] = 0.f;
#pragma unroll
    for (int t = 0; t < 4; t++) {
        uint32_t qh[4], ql[4], bh_[4][4], bl_[4][4];
        uint32_t aoff = SMEM_SWIZZLE_128B((uint32_t)((m0 + ar) * 128 + t * 32 + ac16 * 16));
        ldsm4(qh, sb + OQ_H + aoff);
        ldsm4(ql, sb + OQ_L + aoff);
#pragma unroll
        for (int g = 0; g < 4; g++) {
            uint32_t boff = SMEM_SWIZZLE_128B((uint32_t)((g * 16 + brow) * 128 + t * 32 + bcsel));
            ldsm4(bh_[g], sb + OM_H + boff);
            ldsm4(bl_[g], sb + OM_L + boff);
        }
#pragma unroll
        for (int nj = 0; nj < 8; nj++) {
            int g = nj >> 1, s2 = nj & 1;
            mma16816(oacc[nj], qh, bh_[g][s2], bh_[g][s2 + 2]);
            mma16816(oacc[nj], qh, bl_[g][s2], bl_[g][s2 + 2]);
            mma16816(oacc[nj], ql, bh_[g][s2], bh_[g][s2 + 2]);
        }
    }
#pragma unroll
    for (int j = 0; j < 4; j++) {              // k-tile over s = 16j..16j+15
        uint32_t bh_[4][4], bl_[4][4];
#pragma unroll
        for (int g = 0; g < 4; g++) {
            uint32_t boff = SMEM_SWIZZLE_128B((uint32_t)((g * 16 + brow) * 128 + j * 32 + bcsel));
            ldsm4(bh_[g], sb + OB_H + boff);
            ldsm4(bl_[g], sb + OB_L + boff);
        }
#pragma unroll
        for (int nj = 0; nj < 8; nj++) {
            int g = nj >> 1, s2 = nj & 1;
            mma16816(oacc[nj], sh[j], bh_[g][s2], bh_[g][s2 + 2]);
            mma16816(oacc[nj], sh[j], bl_[g][s2], bl_[g][s2 + 2]);
            mma16816(oacc[nj], sl[j], bh_[g][s2], bh_[g][s2 + 2]);
        }
    }

    // epilogue: split fp32 -> bf16 hi/lo gmem
#pragma unroll
    for (int nj = 0; nj < 8; nj++) {
        int col = nj * 8 + c2;
        uint32_t h0, l0, h1, l1;
        split2(oacc[nj][0], oacc[nj][1], h0, l0);
        split2(oacc[nj][2], oacc[nj][3], h1, l1);
        size_t r0o = base + (size_t)row0 * QAB + col;
        size_t r1o = base + (size_t)row1 * QAB + col;
        *reinterpret_cast<uint32_t*>(g_oh + r0o) = h0;
        *reinterpret_cast<uint32_t*>(g_ol + r0o) = l0;
        *reinterpret_cast<uint32_t*>(g_oh + r1o) = h1;
        *reinterpret_cast<uint32_t*>(g_ol + r1o) = l1;
    }
}

// ---------------- launcher ----------------
extern "C" void kernel_launch(void* const* d_in, const int* in_sizes, int n_in,
                              void* d_out, int out_size) {
    const float* x  = (const float*)d_in[0];
    const float* Wq = (const float*)d_in[1];
    const float* Wa = (const float*)d_in[2];
    const float* Wb = (const float*)d_in[3];
    const float* Wo = (const float*)d_in[4];
    const float* qg = (const float*)d_in[5];
    const float* qb = (const float*)d_in[6];
    const float* ag = (const float*)d_in[7];
    const float* ab = (const float*)d_in[8];
    const float* bg = (const float*)d_in[9];
    const float* bbv = (const float*)d_in[10];
    float* out = (float*)d_out;

    cudaFuncSetAttribute(proj_tc_kernel, cudaFuncAttributeMaxDynamicSharedMemorySize, GM_SMEM);
    cudaFuncSetAttribute(out_tc_kernel,  cudaFuncAttributeMaxDynamicSharedMemorySize, GM_SMEM);
    cudaFuncSetAttribute(attn_kernel,    cudaFuncAttributeMaxDynamicSharedMemorySize, ATT_SMEM);

    split_kernel<<<4096, 256>>>(x);                              // launch 0
    wsplit2_kernel<<<dim3(32, 32, 2), 256>>>(Wq, Wa, 0);         // launch 1
    wsplit2_kernel<<<dim3(32, 32, 2), 256>>>(Wb, Wo, 2);         // launch 2

    proj_tc_kernel<<<dim3(24, 32), 256, GM_SMEM>>>(qg, qb, ag, ab, bg, bbv);  // launch 3 (profiled)

    chunksum_kernel<<<(Bb * QAB * NC) / 256, 256>>>();
    excl_kernel<<<(Bb * QAB * NC) / 256, 256>>>();

    chunkP_kernel<<<Bb * Hh * NC, 256>>>();
    scanM_kernel<<<(Bb * Hh * 4096) / 256, 256>>>();
    attn_kernel<<<Bb * Hh * NC, 128, ATT_SMEM>>>();

    out_tc_kernel<<<dim3(8, 32), 256, GM_SMEM>>>(out);
}

// round 12
// speedup vs baseline: 1.2862x; 1.2862x over previous
#include <cuda_runtime.h>
#include <cuda_fp16.h>
#include <cuda_bf16.h>
#include <cstdint>

#define Bb   2
#define Tt   2048
#define DM   1024
#define Hh   16
#define Dd   64
#define BT   4096          // B*T
#define QAB  1024          // H*D
#define CH   64            // chunk length
#define NC   32            // T / CH

#define OSCALE 64.0f
#define ISCALE (1.0f / 64.0f)

// ---------------- scratch (device globals; no allocs allowed) ----------------
__device__ float g_q  [BT * QAB];
__device__ float g_a  [BT * QAB];
__device__ float g_b  [BT * QAB];
__device__ float g_aex[BT * QAB];
__device__ float g_P  [Bb * Hh * NC * Dd * Dd];   // stored TRANSPOSED: [e][d]
__device__ float g_M  [Bb * Hh * NC * Dd * Dd];   // exclusive scan of P^T = M^T
__device__ float g_cs [Bb * QAB * NC];

// fp16 split operands (A-side exact hi+lo; weights rounded once)
__device__ __half g_xh[BT * DM];
__device__ __half g_xl[BT * DM];
__device__ __half g_oh[BT * QAB];     // holds o/64 hi
__device__ __half g_ol[BT * QAB];     // holds o/64 lo
__device__ __half g_wh[4u << 20];     // 4 weights, each [N=1024][K=1024] (transposed)

// ================= helpers ==================
__device__ __forceinline__ uint32_t smem_u32(const void* p) {
    uint32_t a;
    asm("{ .reg .u64 t; cvta.to.shared.u64 t, %1; cvt.u32.u64 %0, t; }" : "=r"(a) : "l"(p));
    return a;
}
#define SMEM_SWIZZLE_128B(off) ((off) ^ (((off) >> 3) & 0x70))

__device__ __forceinline__ void cp16(uint32_t dst, const void* src) {
    asm volatile("cp.async.cg.shared.global [%0], [%1], 16;" :: "r"(dst), "l"(src));
}
#define CP_COMMIT() asm volatile("cp.async.commit_group;" ::: "memory")

__device__ __forceinline__ void ldsm4(uint32_t* r, uint32_t a) {
    asm volatile("ldmatrix.sync.aligned.m8n8.x4.shared.b16 {%0,%1,%2,%3}, [%4];"
                 : "=r"(r[0]), "=r"(r[1]), "=r"(r[2]), "=r"(r[3]) : "r"(a));
}

__device__ __forceinline__ void mma16816h(float* c, const uint32_t* a,
                                          uint32_t b0, uint32_t b1) {
    asm volatile(
        "mma.sync.aligned.m16n8k16.row.col.f32.f16.f16.f32 "
        "{%0,%1,%2,%3}, {%4,%5,%6,%7}, {%8,%9}, {%0,%1,%2,%3};"
        : "+f"(c[0]), "+f"(c[1]), "+f"(c[2]), "+f"(c[3])
        : "r"(a[0]), "r"(a[1]), "r"(a[2]), "r"(a[3]), "r"(b0), "r"(b1));
}

__device__ __forceinline__ void mma16816b(float* c, const uint32_t* a,
                                          uint32_t b0, uint32_t b1) {
    asm volatile(
        "mma.sync.aligned.m16n8k16.row.col.f32.bf16.bf16.f32 "
        "{%0,%1,%2,%3}, {%4,%5,%6,%7}, {%8,%9}, {%0,%1,%2,%3};"
        : "+f"(c[0]), "+f"(c[1]), "+f"(c[2]), "+f"(c[3])
        : "r"(a[0]), "r"(a[1]), "r"(a[2]), "r"(a[3]), "r"(b0), "r"(b1));
}

// pack two fp32 into fp16x2 hi/lo splits
__device__ __forceinline__ void split2h(float x, float y, uint32_t& hi, uint32_t& lo) {
    __half hx = __float2half(x), hy = __float2half(y);
    float rx = x - __half2float(hx), ry = y - __half2float(hy);
    __half lx = __float2half(rx), ly = __float2half(ry);
    hi = ((uint32_t)__half_as_ushort(hy) << 16) | (uint32_t)__half_as_ushort(hx);
    lo = ((uint32_t)__half_as_ushort(ly) << 16) | (uint32_t)__half_as_ushort(lx);
}
// pack two fp32 into bf16x2 hi/lo splits
__device__ __forceinline__ void split2b(float x, float y, uint32_t& hi, uint32_t& lo) {
    __nv_bfloat16 hx = __float2bfloat16(x), hy = __float2bfloat16(y);
    float rx = x - __bfloat162float(hx), ry = y - __bfloat162float(hy);
    __nv_bfloat16 lx = __float2bfloat16(rx), ly = __float2bfloat16(ry);
    hi = ((uint32_t)__bfloat16_as_ushort(hy) << 16) | (uint32_t)__bfloat16_as_ushort(hx);
    lo = ((uint32_t)__bfloat16_as_ushort(ly) << 16) | (uint32_t)__bfloat16_as_ushort(lx);
}

// ================= HMMA GEMM: C = oscale*(Ah+Al fp16) @ Wh^T ================
// A exact via hi+lo fp16; W rounded once -> error ~2.8e-4 (W rounding only).
// CTA tile 128x128, BK=64, 3-stage cp.async ring, 512 threads, warp 16x64.
#define GM_STAGE 49152                 // Ah 16K | Al 16K | Bh 16K
#define GM_SMEM  (3 * GM_STAGE)

__device__ __forceinline__ void gemm_mma(const __half* __restrict__ Ah,
                                         const __half* __restrict__ Al,
                                         const __half* __restrict__ Bh,
                                         float* __restrict__ C, int ldc,
                                         int bm, int bn,
                                         const float* __restrict__ gamma,
                                         const float* __restrict__ beta,
                                         float oscale) {
    extern __shared__ char smem[];
    const uint32_t sb = smem_u32(smem);
    const int tid = threadIdx.x, wid = tid >> 5, lane = tid & 31;
    const int m0 = (wid >> 1) * 16;     // warp row base (8 rows of warps)
    const int n0 = (wid & 1) * 64;      // warp col base (2 cols of warps)

    float acc[8][4];
#pragma unroll
    for (int j = 0; j < 8; j++)
#pragma unroll
        for (int k = 0; k < 4; k++) acc[j][k] = 0.f;

    auto load_stage = [&](int st, int k0) {
        uint32_t base = sb + st * GM_STAGE;
#pragma unroll
        for (int tile = 0; tile < 3; tile++) {
            const __half* src = tile == 0 ? Ah : tile == 1 ? Al : Bh;
            const int rb = (tile < 2) ? bm : bn;
#pragma unroll
            for (int s = tid; s < 1024; s += 512) {
                int row = s >> 3, ks = s & 7;
                uint32_t dst = base + tile * 16384 +
                               SMEM_SWIZZLE_128B((uint32_t)(row * 128 + ks * 16));
                cp16(dst, src + (size_t)(rb + row) * 1024 + k0 + ks * 8);
            }
        }
        CP_COMMIT();
    };

    const int ar  = lane & 15, ac16 = lane >> 4;             // A 16x16
    const int bsub = lane >> 3, br8 = lane & 7;              // B 16x16
    const int brow = ((bsub & 1) ? 8 : 0) + br8;
    const int bcsel = (bsub >> 1) ? 16 : 0;

    load_stage(0, 0);       // chunk 0 -> buf 0
    load_stage(1, 64);      // chunk 1 -> buf 1
    for (int i = 0; i < 16; i++) {
        asm volatile("cp.async.wait_group 1;" ::: "memory");   // chunk-i groups done
        __syncthreads();                                       // buf i%3 valid CTA-wide

        if (i < 14) load_stage((i + 2) % 3, (i + 2) * 64);     // prefetch, overlaps MMA
        else CP_COMMIT();                  // empty group keeps wait_group counts aligned

        const uint32_t ahb = sb + (i % 3) * GM_STAGE;
        const uint32_t alb = ahb + 16384, bhb = ahb + 32768;

#pragma unroll
        for (int t = 0; t < 4; t++) {
            uint32_t ahf[4], alf[4], bhf[4][4];
            uint32_t aoff = SMEM_SWIZZLE_128B(
                (uint32_t)((m0 + ar) * 128 + t * 32 + ac16 * 16));
            ldsm4(ahf, ahb + aoff);
            ldsm4(alf, alb + aoff);
#pragma unroll
            for (int g = 0; g < 4; g++) {
                uint32_t off = SMEM_SWIZZLE_128B(
                    (uint32_t)((n0 + g * 16 + brow) * 128 + t * 32 + bcsel));
                ldsm4(bhf[g], bhb + off);
            }
#pragma unroll
            for (int nj = 0; nj < 8; nj++) {
                int g = nj >> 1, s2 = nj & 1;
                mma16816h(acc[nj], ahf, bhf[g][s2], bhf[g][s2 + 2]);
                mma16816h(acc[nj], alf, bhf[g][s2], bhf[g][s2 + 2]);
            }
        }
    }

    const int r4 = lane >> 2, c2 = (lane & 3) * 2;

    // -------- fused per-head LayerNorm (head == warp's 64-col span) --------
    if (gamma) {
        float gv[16], bv[16];
#pragma unroll
        for (int nj = 0; nj < 8; nj++)
#pragma unroll
            for (int t = 0; t < 2; t++) {
                int d = nj * 8 + c2 + t;
                gv[nj * 2 + t] = __ldg(gamma + d);
                bv[nj * 2 + t] = __ldg(beta + d);
            }
        float s0 = 0.f, q0 = 0.f, s1 = 0.f, q1 = 0.f;
#pragma unroll
        for (int nj = 0; nj < 8; nj++) {
            float v0 = acc[nj][0], v1 = acc[nj][1];
            float v2 = acc[nj][2], v3 = acc[nj][3];
            s0 += v0 + v1; q0 += v0 * v0 + v1 * v1;
            s1 += v2 + v3; q1 += v2 * v2 + v3 * v3;
        }
#pragma unroll
        for (int o = 1; o <= 2; o <<= 1) {
            s0 += __shfl_xor_sync(0xFFFFFFFFu, s0, o);
            q0 += __shfl_xor_sync(0xFFFFFFFFu, q0, o);
            s1 += __shfl_xor_sync(0xFFFFFFFFu, s1, o);
            q1 += __shfl_xor_sync(0xFFFFFFFFu, q1, o);
        }
        float m0s = s0 * (1.f / 64.f);
        float r0 = rsqrtf(q0 * (1.f / 64.f) - m0s * m0s + 1e-5f);
        float m1s = s1 * (1.f / 64.f);
        float r1 = rsqrtf(q1 * (1.f / 64.f) - m1s * m1s + 1e-5f);
#pragma unroll
        for (int nj = 0; nj < 8; nj++) {
            acc[nj][0] = (acc[nj][0] - m0s) * r0 * gv[nj * 2]     + bv[nj * 2];
            acc[nj][1] = (acc[nj][1] - m0s) * r0 * gv[nj * 2 + 1] + bv[nj * 2 + 1];
            acc[nj][2] = (acc[nj][2] - m1s) * r1 * gv[nj * 2]     + bv[nj * 2];
            acc[nj][3] = (acc[nj][3] - m1s) * r1 * gv[nj * 2 + 1] + bv[nj * 2 + 1];
        }
    }

    // epilogue: c frag * oscale -> gmem fp32
#pragma unroll
    for (int nj = 0; nj < 8; nj++) {
        int m = bm + m0 + r4;
        int n = bn + n0 + nj * 8 + c2;
        float2 v0 = make_float2(acc[nj][0] * oscale, acc[nj][1] * oscale);
        float2 v1 = make_float2(acc[nj][2] * oscale, acc[nj][3] * oscale);
        *reinterpret_cast<float2*>(C + (size_t)m * ldc + n) = v0;
        *reinterpret_cast<float2*>(C + (size_t)(m + 8) * ldc + n) = v1;
    }
}

__global__ __launch_bounds__(512, 1) void proj_tc_kernel(const float* __restrict__ qg,
                                                         const float* __restrict__ qb,
                                                         const float* __restrict__ ag,
                                                         const float* __restrict__ ab,
                                                         const float* __restrict__ bg,
                                                         const float* __restrict__ bbv) {
    const int w = blockIdx.x >> 3, nt = blockIdx.x & 7, bm = blockIdx.y * 128;
    const __half* Bh = g_wh + ((size_t)w << 20);
    float* C;
    const float* gm;
    const float* bt;
    if (w == 0)      { C = g_q; gm = qg; bt = qb; }
    else if (w == 1) { C = g_a; gm = ag; bt = ab; }
    else             { C = g_b; gm = bg; bt = bbv; }
    gemm_mma(g_xh, g_xl, Bh, C, QAB, bm, nt * 128, gm, bt, 1.0f);
}

__global__ __launch_bounds__(512, 1) void out_tc_kernel(float* __restrict__ out) {
    const int nt = blockIdx.x, bm = blockIdx.y * 128;
    const __half* Bh = g_wh + ((size_t)3 << 20);
    // A-side holds o/64; restore with oscale = 64
    gemm_mma(g_oh, g_ol, Bh, out, DM, bm, nt * 128, nullptr, nullptr, OSCALE);
}

// ---------------- split fp32 x -> hi/lo fp16 ----------------
__global__ __launch_bounds__(256) void split_kernel(const float* __restrict__ in) {
    size_t i = ((size_t)blockIdx.x * 256 + threadIdx.x) * 4;
    float4 v = *reinterpret_cast<const float4*>(in + i);
    float vv[4] = {v.x, v.y, v.z, v.w};
#pragma unroll
    for (int j = 0; j < 4; j++) {
        __half h = __float2half(vv[j]);
        g_xh[i + j] = h;
        g_xl[i + j] = __float2half(vv[j] - __half2float(h));
    }
}

// weights: fp32 [K=1024, N=1024] -> transposed fp16 [N, K]; 2 weights/launch
__global__ __launch_bounds__(256) void wsplit2_kernel(const float* __restrict__ WA,
                                                      const float* __restrict__ WB,
                                                      int wbase) {
    const float* W = (blockIdx.z == 0) ? WA : WB;
    const int widx = wbase + blockIdx.z;
    __shared__ float t[32][33];
    const int bx = blockIdx.x * 32;   // n
    const int by = blockIdx.y * 32;   // k
    const int tx = threadIdx.x & 31, ty = threadIdx.x >> 5;
#pragma unroll
    for (int r = 0; r < 32; r += 8)
        t[ty + r][tx] = W[(size_t)(by + ty + r) * 1024 + bx + tx];
    __syncthreads();
    __half* oh = g_wh + ((size_t)widx << 20);
#pragma unroll
    for (int r = 0; r < 32; r += 8) {
        float v = t[tx][ty + r];                          // = W[by+tx][bx+ty+r]
        size_t oi = (size_t)(bx + ty + r) * 1024 + by + tx;
        oh[oi] = __float2half(v);
    }
}

// ---------------- exclusive cumsum of a along time (two-pass) ----------------
__global__ __launch_bounds__(256) void chunksum_kernel() {
    int gid = blockIdx.x * 256 + threadIdx.x;
    int col = gid % QAB;
    int c   = (gid / QAB) % NC;
    int b   = gid / (QAB * NC);
    const float* p = g_a + (size_t)(b * Tt + c * CH) * QAB + col;
    float s = 0.f;
#pragma unroll 8
    for (int r = 0; r < CH; r++) s += p[(size_t)r * QAB];
    g_cs[(b * NC + c) * QAB + col] = s;
}

__global__ __launch_bounds__(256) void excl_kernel() {
    int gid = blockIdx.x * 256 + threadIdx.x;
    int col = gid % QAB;
    int c   = (gid / QAB) % NC;
    int b   = gid / (QAB * NC);
    float off = 0.f;
    for (int cc = 0; cc < c; cc++) off += g_cs[(b * NC + cc) * QAB + col];
    const float* pa = g_a   + (size_t)(b * Tt + c * CH) * QAB + col;
    float*       pe = g_aex + (size_t)(b * Tt + c * CH) * QAB + col;
    float run = off;
#pragma unroll 8
    for (int r = 0; r < CH; r++) {
        pe[(size_t)r * QAB] = run;
        run += pa[(size_t)r * QAB];
    }
}

// -------- per-chunk outer product, stored transposed: P^T[e][d] = sum_t B[t][e] Aex[t][d]
__global__ __launch_bounds__(256) void chunkP_kernel() {
    int c = blockIdx.x & (NC - 1);
    int h = (blockIdx.x >> 5) & (Hh - 1);
    int b = blockIdx.x >> 9;
    __shared__ float Ax[64][64];
    __shared__ float Bx[64][64];
    int tid = threadIdx.x;
    size_t base = (size_t)(b * Tt + c * CH) * QAB + h * Dd;
    for (int idx = tid; idx < 4096; idx += 256) {
        int t = idx >> 6, d = idx & 63;
        Ax[t][d] = g_aex[base + (size_t)t * QAB + d];
        Bx[t][d] = g_b [base + (size_t)t * QAB + d];
    }
    __syncthreads();
    int dr = (tid >> 4) * 4, ec = (tid & 15) * 4;
    float acc[4][4] = {};
#pragma unroll 4
    for (int t = 0; t < 64; t++) {
        float av[4], bv[4];
#pragma unroll
        for (int i = 0; i < 4; i++) av[i] = Ax[t][dr + i];
#pragma unroll
        for (int j = 0; j < 4; j++) bv[j] = Bx[t][ec + j];
#pragma unroll
        for (int i = 0; i < 4; i++)
#pragma unroll
            for (int j = 0; j < 4; j++)
                acc[i][j] = fmaf(av[i], bv[j], acc[i][j]);
    }
    size_t pb = ((size_t)((b * Hh + h) * NC + c)) * 4096;
#pragma unroll
    for (int j = 0; j < 4; j++) {       // transposed store: row e, col d
        float4 v = make_float4(acc[0][j], acc[1][j], acc[2][j], acc[3][j]);
        *reinterpret_cast<float4*>(g_P + pb + (size_t)(ec + j) * 64 + dr) = v;
    }
}

// ---------------- elementwise exclusive scan of P^T over chunks -> M^T -------
__global__ __launch_bounds__(256) void scanM_kernel() {
    int gid = blockIdx.x * 256 + threadIdx.x;
    int de = gid & 4095;
    int bh = gid >> 12;
    size_t base = (size_t)bh * NC * 4096 + de;
    float run = 0.f;
#pragma unroll
    for (int c = 0; c < NC; c++) {
        g_M[base + (size_t)c * 4096] = run;
        run += g_P[base + (size_t)c * 4096];
    }
}

// ---------------- chunk attention via HMMA (bf16 3-term internals) -----------
// S = tril(Q Aex^T);  O = Q M^T_rows + S B^T_rows;  output -> (o/64) fp16 splits
#define OQ_H 0
#define OQ_L 8192
#define OA_H 16384
#define OA_L 24576
#define OB_H 32768
#define OB_L 40960
#define OM_H 49152
#define OM_L 57344
#define ATT_SMEM 65536

__global__ __launch_bounds__(128, 1) void attn_kernel() {
    extern __shared__ char smem[];
    const uint32_t sb = smem_u32(smem);
    int c = blockIdx.x & (NC - 1);
    int h = (blockIdx.x >> 5) & (Hh - 1);
    int b = blockIdx.x >> 9;
    int tid = threadIdx.x, wid = tid >> 5, lane = tid & 31;
    size_t base  = (size_t)(b * Tt + c * CH) * QAB + h * Dd;
    size_t mbase = ((size_t)((b * Hh + h) * NC + c)) * 4096;

    // load + convert to split bf16 smem (SW128 rows of 128B)
    for (int idx = tid; idx < 4096; idx += 128) {
        int t = idx >> 6, d = idx & 63;
        size_t go = base + (size_t)t * QAB + d;
        float q  = g_q[go];
        float a  = g_aex[go];
        float bv = g_b[go];
        float m  = g_M[mbase + idx];                       // row e=t, col d (M^T)
        uint32_t offr = SMEM_SWIZZLE_128B((uint32_t)(t * 128 + d * 2));
        uint32_t offt = SMEM_SWIZZLE_128B((uint32_t)(d * 128 + t * 2));  // B transposed
        __nv_bfloat16 hh, ll;
        hh = __float2bfloat16(q);  ll = __float2bfloat16(q - __bfloat162float(hh));
        *(__nv_bfloat16*)(smem + OQ_H + offr) = hh;
        *(__nv_bfloat16*)(smem + OQ_L + offr) = ll;
        hh = __float2bfloat16(a);  ll = __float2bfloat16(a - __bfloat162float(hh));
        *(__nv_bfloat16*)(smem + OA_H + offr) = hh;
        *(__nv_bfloat16*)(smem + OA_L + offr) = ll;
        hh = __float2bfloat16(bv); ll = __float2bfloat16(bv - __bfloat162float(hh));
        *(__nv_bfloat16*)(smem + OB_H + offt) = hh;
        *(__nv_bfloat16*)(smem + OB_L + offt) = ll;
        hh = __float2bfloat16(m);  ll = __float2bfloat16(m - __bfloat162float(hh));
        *(__nv_bfloat16*)(smem + OM_H + offr) = hh;
        *(__nv_bfloat16*)(smem + OM_L + offr) = ll;
    }
    __syncthreads();

    const int m0 = wid * 16;
    const int ar = lane & 15, ac16 = lane >> 4;
    const int bsub = lane >> 3, br8 = lane & 7;
    const int brow = ((bsub & 1) ? 8 : 0) + br8;
    const int bcsel = (bsub >> 1) ? 16 : 0;
    const int r4 = lane >> 2, c2 = (lane & 3) * 2;

    // ---- gemm1: S = Q @ Aex^T ----
    float sacc[8][4];
#pragma unroll
    for (int j = 0; j < 8; j++)
#pragma unroll
        for (int k = 0; k < 4; k++) sacc[j][k] = 0.f;
#pragma unroll
    for (int t = 0; t < 4; t++) {
        uint32_t qh[4], ql[4], bh_[4][4], bl_[4][4];
        uint32_t aoff = SMEM_SWIZZLE_128B((uint32_t)((m0 + ar) * 128 + t * 32 + ac16 * 16));
        ldsm4(qh, sb + OQ_H + aoff);
        ldsm4(ql, sb + OQ_L + aoff);
#pragma unroll
        for (int g = 0; g < 4; g++) {
            uint32_t boff = SMEM_SWIZZLE_128B((uint32_t)((g * 16 + brow) * 128 + t * 32 + bcsel));
            ldsm4(bh_[g], sb + OA_H + boff);
            ldsm4(bl_[g], sb + OA_L + boff);
        }
#pragma unroll
        for (int nj = 0; nj < 8; nj++) {
            int g = nj >> 1, s2 = nj & 1;
            mma16816b(sacc[nj], qh, bh_[g][s2], bh_[g][s2 + 2]);
            mma16816b(sacc[nj], qh, bl_[g][s2], bl_[g][s2 + 2]);
            mma16816b(sacc[nj], ql, bh_[g][s2], bh_[g][s2 + 2]);
        }
    }

    // causal mask (keep s <= t)
    const int row0 = m0 + r4, row1 = row0 + 8;
#pragma unroll
    for (int nj = 0; nj < 8; nj++) {
        int col = nj * 8 + c2;
        if (col     > row0) sacc[nj][0] = 0.f;
        if (col + 1 > row0) sacc[nj][1] = 0.f;
        if (col     > row1) sacc[nj][2] = 0.f;
        if (col + 1 > row1) sacc[nj][3] = 0.f;
    }

    // S C-frags -> A-frags (hi/lo bf16), pure register repack
    uint32_t sh[4][4], sl[4][4];
#pragma unroll
    for (int j = 0; j < 4; j++) {
        split2b(sacc[2 * j][0],     sacc[2 * j][1],     sh[j][0], sl[j][0]);
        split2b(sacc[2 * j][2],     sacc[2 * j][3],     sh[j][1], sl[j][1]);
        split2b(sacc[2 * j + 1][0], sacc[2 * j + 1][1], sh[j][2], sl[j][2]);
        split2b(sacc[2 * j + 1][2], sacc[2 * j + 1][3], sh[j][3], sl[j][3]);
    }

    // ---- gemm2: O = Q @ M^T  (+ gemm3: O += S @ B^T) ----
    float oacc[8][4];
#pragma unroll
    for (int j = 0; j < 8; j++)
#pragma unroll
        for (int k = 0; k < 4; k++) oacc[j][k] = 0.f;
#pragma unroll
    for (int t = 0; t < 4; t++) {
        uint32_t qh[4], ql[4], bh_[4][4], bl_[4][4];
        uint32_t aoff = SMEM_SWIZZLE_128B((uint32_t)((m0 + ar) * 128 + t * 32 + ac16 * 16));
        ldsm4(qh, sb + OQ_H + aoff);
        ldsm4(ql, sb + OQ_L + aoff);
#pragma unroll
        for (int g = 0; g < 4; g++) {
            uint32_t boff = SMEM_SWIZZLE_128B((uint32_t)((g * 16 + brow) * 128 + t * 32 + bcsel));
            ldsm4(bh_[g], sb + OM_H + boff);
            ldsm4(bl_[g], sb + OM_L + boff);
        }
#pragma unroll
        for (int nj = 0; nj < 8; nj++) {
            int g = nj >> 1, s2 = nj & 1;
            mma16816b(oacc[nj], qh, bh_[g][s2], bh_[g][s2 + 2]);
            mma16816b(oacc[nj], qh, bl_[g][s2], bl_[g][s2 + 2]);
            mma16816b(oacc[nj], ql, bh_[g][s2], bh_[g][s2 + 2]);
        }
    }
#pragma unroll
    for (int j = 0; j < 4; j++) {              // k-tile over s = 16j..16j+15
        uint32_t bh_[4][4], bl_[4][4];
#pragma unroll
        for (int g = 0; g < 4; g++) {
            uint32_t boff = SMEM_SWIZZLE_128B((uint32_t)((g * 16 + brow) * 128 + j * 32 + bcsel));
            ldsm4(bh_[g], sb + OB_H + boff);
            ldsm4(bl_[g], sb + OB_L + boff);
        }
#pragma unroll
        for (int nj = 0; nj < 8; nj++) {
            int g = nj >> 1, s2 = nj & 1;
            mma16816b(oacc[nj], sh[j], bh_[g][s2], bh_[g][s2 + 2]);
            mma16816b(oacc[nj], sh[j], bl_[g][s2], bl_[g][s2 + 2]);
            mma16816b(oacc[nj], sl[j], bh_[g][s2], bh_[g][s2 + 2]);
        }
    }

    // epilogue: (o/64) fp32 -> fp16 hi/lo gmem (fp16-safe after scaling)
#pragma unroll
    for (int nj = 0; nj < 8; nj++) {
        int col = nj * 8 + c2;
        uint32_t h0, l0, h1, l1;
        split2h(oacc[nj][0] * ISCALE, oacc[nj][1] * ISCALE, h0, l0);
        split2h(oacc[nj][2] * ISCALE, oacc[nj][3] * ISCALE, h1, l1);
        size_t r0o = base + (size_t)row0 * QAB + col;
        size_t r1o = base + (size_t)row1 * QAB + col;
        *reinterpret_cast<uint32_t*>(g_oh + r0o) = h0;
        *reinterpret_cast<uint32_t*>(g_ol + r0o) = l0;
        *reinterpret_cast<uint32_t*>(g_oh + r1o) = h1;
        *reinterpret_cast<uint32_t*>(g_ol + r1o) = l1;
    }
}

// ---------------- launcher ----------------
extern "C" void kernel_launch(void* const* d_in, const int* in_sizes, int n_in,
                              void* d_out, int out_size) {
    const float* x  = (const float*)d_in[0];
    const float* Wq = (const float*)d_in[1];
    const float* Wa = (const float*)d_in[2];
    const float* Wb = (const float*)d_in[3];
    const float* Wo = (const float*)d_in[4];
    const float* qg = (const float*)d_in[5];
    const float* qb = (const float*)d_in[6];
    const float* ag = (const float*)d_in[7];
    const float* ab = (const float*)d_in[8];
    const float* bg = (const float*)d_in[9];
    const float* bbv = (const float*)d_in[10];
    float* out = (float*)d_out;

    cudaFuncSetAttribute(proj_tc_kernel, cudaFuncAttributeMaxDynamicSharedMemorySize, GM_SMEM);
    cudaFuncSetAttribute(out_tc_kernel,  cudaFuncAttributeMaxDynamicSharedMemorySize, GM_SMEM);
    cudaFuncSetAttribute(attn_kernel,    cudaFuncAttributeMaxDynamicSharedMemorySize, ATT_SMEM);

    split_kernel<<<4096, 256>>>(x);                              // launch 0
    wsplit2_kernel<<<dim3(32, 32, 2), 256>>>(Wq, Wa, 0);         // launch 1
    wsplit2_kernel<<<dim3(32, 32, 2), 256>>>(Wb, Wo, 2);         // launch 2

    proj_tc_kernel<<<dim3(24, 32), 512, GM_SMEM>>>(qg, qb, ag, ab, bg, bbv);  // launch 3 (profiled)

    chunksum_kernel<<<(Bb * QAB * NC) / 256, 256>>>();
    excl_kernel<<<(Bb * QAB * NC) / 256, 256>>>();

    chunkP_kernel<<<Bb * Hh * NC, 256>>>();
    scanM_kernel<<<(Bb * Hh * 4096) / 256, 256>>>();
    attn_kernel<<<Bb * Hh * NC, 128, ATT_SMEM>>>();

    out_tc_kernel<<<dim3(8, 32), 512, GM_SMEM>>>(out);
}

// round 13
// speedup vs baseline: 1.6228x; 1.2617x over previous
#include <cuda_runtime.h>
#include <cuda_fp16.h>
#include <cuda_bf16.h>
#include <cstdint>

#define Bb   2
#define Tt   2048
#define DM   1024
#define Hh   16
#define Dd   64
#define BT   4096          // B*T
#define QAB  1024          // H*D
#define CH   64            // chunk length
#define NC   32            // T / CH

#define OSCALE 64.0f
#define ISCALE (1.0f / 64.0f)

// ---------------- scratch (device globals; no allocs allowed) ----------------
__device__ float g_q  [BT * QAB];
__device__ float g_a  [BT * QAB];
__device__ float g_b  [BT * QAB];
__device__ float g_aex[BT * QAB];
__device__ float g_P  [Bb * Hh * NC * Dd * Dd];   // stored TRANSPOSED: [e][d]
__device__ float g_M  [Bb * Hh * NC * Dd * Dd];   // exclusive scan of P^T = M^T
__device__ float g_cs [Bb * QAB * NC];

// fp16 operands
__device__ __half g_xh[BT * DM];      // x rounded (1-term proj)
__device__ __half g_oh[BT * QAB];     // o/64 hi
__device__ __half g_ol[BT * QAB];     // o/64 lo (2-term out GEMM)
__device__ __half g_wh[4u << 20];     // 4 weights, each [N=1024][K=1024] (transposed)

// ================= helpers ==================
__device__ __forceinline__ uint32_t smem_u32(const void* p) {
    uint32_t a;
    asm("{ .reg .u64 t; cvta.to.shared.u64 t, %1; cvt.u32.u64 %0, t; }" : "=r"(a) : "l"(p));
    return a;
}
#define SMEM_SWIZZLE_128B(off) ((off) ^ (((off) >> 3) & 0x70))

__device__ __forceinline__ void cp16(uint32_t dst, const void* src) {
    asm volatile("cp.async.cg.shared.global [%0], [%1], 16;" :: "r"(dst), "l"(src));
}
#define CP_COMMIT() asm volatile("cp.async.commit_group;" ::: "memory")

__device__ __forceinline__ void ldsm4(uint32_t* r, uint32_t a) {
    asm volatile("ldmatrix.sync.aligned.m8n8.x4.shared.b16 {%0,%1,%2,%3}, [%4];"
                 : "=r"(r[0]), "=r"(r[1]), "=r"(r[2]), "=r"(r[3]) : "r"(a));
}

__device__ __forceinline__ void mma16816h(float* c, const uint32_t* a,
                                          uint32_t b0, uint32_t b1) {
    asm volatile(
        "mma.sync.aligned.m16n8k16.row.col.f32.f16.f16.f32 "
        "{%0,%1,%2,%3}, {%4,%5,%6,%7}, {%8,%9}, {%0,%1,%2,%3};"
        : "+f"(c[0]), "+f"(c[1]), "+f"(c[2]), "+f"(c[3])
        : "r"(a[0]), "r"(a[1]), "r"(a[2]), "r"(a[3]), "r"(b0), "r"(b1));
}

__device__ __forceinline__ void mma16816b(float* c, const uint32_t* a,
                                          uint32_t b0, uint32_t b1) {
    asm volatile(
        "mma.sync.aligned.m16n8k16.row.col.f32.bf16.bf16.f32 "
        "{%0,%1,%2,%3}, {%4,%5,%6,%7}, {%8,%9}, {%0,%1,%2,%3};"
        : "+f"(c[0]), "+f"(c[1]), "+f"(c[2]), "+f"(c[3])
        : "r"(a[0]), "r"(a[1]), "r"(a[2]), "r"(a[3]), "r"(b0), "r"(b1));
}

// pack two fp32 into fp16x2 hi/lo splits
__device__ __forceinline__ void split2h(float x, float y, uint32_t& hi, uint32_t& lo) {
    __half hx = __float2half(x), hy = __float2half(y);
    float rx = x - __half2float(hx), ry = y - __half2float(hy);
    __half lx = __float2half(rx), ly = __float2half(ry);
    hi = ((uint32_t)__half_as_ushort(hy) << 16) | (uint32_t)__half_as_ushort(hx);
    lo = ((uint32_t)__half_as_ushort(ly) << 16) | (uint32_t)__half_as_ushort(lx);
}
// pack two fp32 into bf16x2 hi/lo splits
__device__ __forceinline__ void split2b(float x, float y, uint32_t& hi, uint32_t& lo) {
    __nv_bfloat16 hx = __float2bfloat16(x), hy = __float2bfloat16(y);
    float rx = x - __bfloat162float(hx), ry = y - __bfloat162float(hy);
    __nv_bfloat16 lx = __float2bfloat16(rx), ly = __float2bfloat16(ry);
    hi = ((uint32_t)__bfloat16_as_ushort(hy) << 16) | (uint32_t)__bfloat16_as_ushort(hx);
    lo = ((uint32_t)__bfloat16_as_ushort(ly) << 16) | (uint32_t)__bfloat16_as_ushort(lx);
}

// ================= HMMA GEMM: C = oscale*(A fp16 [1 or 2 term]) @ Wh^T ======
// TERMS=1: A rounded once. TERMS=2: A exact via hi+lo.
// CTA tile 128x128, BK=64, 3-stage cp.async ring, 512 threads, warp 16x64.
template <int TERMS>
__device__ __forceinline__ void gemm_mma(const __half* __restrict__ Ah,
                                         const __half* __restrict__ Al,
                                         const __half* __restrict__ Bh,
                                         float* __restrict__ C, int ldc,
                                         int bm, int bn,
                                         const float* __restrict__ gamma,
                                         const float* __restrict__ beta,
                                         float oscale) {
    constexpr int NTILES = TERMS + 1;          // A tiles + B tile
    constexpr uint32_t STAGE = NTILES * 16384;
    extern __shared__ char smem[];
    const uint32_t sb = smem_u32(smem);
    const int tid = threadIdx.x, wid = tid >> 5, lane = tid & 31;
    const int m0 = (wid >> 1) * 16;     // warp row base (8 rows of warps)
    const int n0 = (wid & 1) * 64;      // warp col base (2 cols of warps)

    float acc[8][4];
#pragma unroll
    for (int j = 0; j < 8; j++)
#pragma unroll
        for (int k = 0; k < 4; k++) acc[j][k] = 0.f;

    auto load_stage = [&](int st, int k0) {
        uint32_t base = sb + st * STAGE;
#pragma unroll
        for (int tile = 0; tile < NTILES; tile++) {
            const __half* src = (tile == 0) ? Ah
                              : (TERMS == 2 && tile == 1) ? Al : Bh;
            const int rb = (tile < NTILES - 1) ? bm : bn;
#pragma unroll
            for (int s = tid; s < 1024; s += 512) {
                int row = s >> 3, ks = s & 7;
                uint32_t dst = base + tile * 16384 +
                               SMEM_SWIZZLE_128B((uint32_t)(row * 128 + ks * 16));
                cp16(dst, src + (size_t)(rb + row) * 1024 + k0 + ks * 8);
            }
        }
        CP_COMMIT();
    };

    const int ar  = lane & 15, ac16 = lane >> 4;             // A 16x16
    const int bsub = lane >> 3, br8 = lane & 7;              // B 16x16
    const int brow = ((bsub & 1) ? 8 : 0) + br8;
    const int bcsel = (bsub >> 1) ? 16 : 0;

    // hoist swizzled intra-stage offsets out of the main loop (kills IMAD churn)
    uint32_t aoffs[4], boffs[4][4];
#pragma unroll
    for (int t = 0; t < 4; t++) {
        aoffs[t] = SMEM_SWIZZLE_128B((uint32_t)((m0 + ar) * 128 + t * 32 + ac16 * 16));
#pragma unroll
        for (int g = 0; g < 4; g++)
            boffs[t][g] = SMEM_SWIZZLE_128B(
                (uint32_t)((n0 + g * 16 + brow) * 128 + t * 32 + bcsel));
    }

    load_stage(0, 0);       // chunk 0 -> buf 0
    load_stage(1, 64);      // chunk 1 -> buf 1
    for (int i = 0; i < 16; i++) {
        asm volatile("cp.async.wait_group 1;" ::: "memory");   // chunk-i groups done
        __syncthreads();                                       // buf i%3 valid CTA-wide

        if (i < 14) load_stage((i + 2) % 3, (i + 2) * 64);     // prefetch, overlaps MMA
        else CP_COMMIT();                  // empty group keeps wait_group counts aligned

        const uint32_t ahb = sb + (i % 3) * STAGE;
        const uint32_t alb = ahb + 16384;                      // valid when TERMS==2
        const uint32_t bhb = ahb + (NTILES - 1) * 16384;

#pragma unroll
        for (int t = 0; t < 4; t++) {
            uint32_t ahf[4], alf[4], bhf[4][4];
            ldsm4(ahf, ahb + aoffs[t]);
            if (TERMS == 2) ldsm4(alf, alb + aoffs[t]);
#pragma unroll
            for (int g = 0; g < 4; g++)
                ldsm4(bhf[g], bhb + boffs[t][g]);
#pragma unroll
            for (int nj = 0; nj < 8; nj++) {
                int g = nj >> 1, s2 = nj & 1;
                mma16816h(acc[nj], ahf, bhf[g][s2], bhf[g][s2 + 2]);
                if (TERMS == 2)
                    mma16816h(acc[nj], alf, bhf[g][s2], bhf[g][s2 + 2]);
            }
        }
    }

    const int r4 = lane >> 2, c2 = (lane & 3) * 2;

    // -------- fused per-head LayerNorm (head == warp's 64-col span) --------
    if (gamma) {
        float gv[16], bv[16];
#pragma unroll
        for (int nj = 0; nj < 8; nj++)
#pragma unroll
            for (int t = 0; t < 2; t++) {
                int d = nj * 8 + c2 + t;
                gv[nj * 2 + t] = __ldg(gamma + d);
                bv[nj * 2 + t] = __ldg(beta + d);
            }
        float s0 = 0.f, q0 = 0.f, s1 = 0.f, q1 = 0.f;
#pragma unroll
        for (int nj = 0; nj < 8; nj++) {
            float v0 = acc[nj][0], v1 = acc[nj][1];
            float v2 = acc[nj][2], v3 = acc[nj][3];
            s0 += v0 + v1; q0 += v0 * v0 + v1 * v1;
            s1 += v2 + v3; q1 += v2 * v2 + v3 * v3;
        }
#pragma unroll
        for (int o = 1; o <= 2; o <<= 1) {
            s0 += __shfl_xor_sync(0xFFFFFFFFu, s0, o);
            q0 += __shfl_xor_sync(0xFFFFFFFFu, q0, o);
            s1 += __shfl_xor_sync(0xFFFFFFFFu, s1, o);
            q1 += __shfl_xor_sync(0xFFFFFFFFu, q1, o);
        }
        float m0s = s0 * (1.f / 64.f);
        float r0 = rsqrtf(q0 * (1.f / 64.f) - m0s * m0s + 1e-5f);
        float m1s = s1 * (1.f / 64.f);
        float r1 = rsqrtf(q1 * (1.f / 64.f) - m1s * m1s + 1e-5f);
#pragma unroll
        for (int nj = 0; nj < 8; nj++) {
            acc[nj][0] = (acc[nj][0] - m0s) * r0 * gv[nj * 2]     + bv[nj * 2];
            acc[nj][1] = (acc[nj][1] - m0s) * r0 * gv[nj * 2 + 1] + bv[nj * 2 + 1];
            acc[nj][2] = (acc[nj][2] - m1s) * r1 * gv[nj * 2]     + bv[nj * 2];
            acc[nj][3] = (acc[nj][3] - m1s) * r1 * gv[nj * 2 + 1] + bv[nj * 2 + 1];
        }
    }

    // epilogue: c frag * oscale -> gmem fp32
#pragma unroll
    for (int nj = 0; nj < 8; nj++) {
        int m = bm + m0 + r4;
        int n = bn + n0 + nj * 8 + c2;
        float2 v0 = make_float2(acc[nj][0] * oscale, acc[nj][1] * oscale);
        float2 v1 = make_float2(acc[nj][2] * oscale, acc[nj][3] * oscale);
        *reinterpret_cast<float2*>(C + (size_t)m * ldc + n) = v0;
        *reinterpret_cast<float2*>(C + (size_t)(m + 8) * ldc + n) = v1;
    }
}

#define GM_SMEM_1 (3 * 32768)
#define GM_SMEM_2 (3 * 49152)

__global__ __launch_bounds__(512, 1) void proj_tc_kernel(const float* __restrict__ qg,
                                                         const float* __restrict__ qb,
                                                         const float* __restrict__ ag,
                                                         const float* __restrict__ ab,
                                                         const float* __restrict__ bg,
                                                         const float* __restrict__ bbv) {
    const int w = blockIdx.x >> 3, nt = blockIdx.x & 7, bm = blockIdx.y * 128;
    const __half* Bh = g_wh + ((size_t)w << 20);
    float* C;
    const float* gm;
    const float* bt;
    if (w == 0)      { C = g_q; gm = qg; bt = qb; }
    else if (w == 1) { C = g_a; gm = ag; bt = ab; }
    else             { C = g_b; gm = bg; bt = bbv; }
    gemm_mma<1>(g_xh, nullptr, Bh, C, QAB, bm, nt * 128, gm, bt, 1.0f);
}

__global__ __launch_bounds__(512, 1) void out_tc_kernel(float* __restrict__ out) {
    const int nt = blockIdx.x, bm = blockIdx.y * 128;
    const __half* Bh = g_wh + ((size_t)3 << 20);
    // A-side holds o/64 exact (hi+lo); restore with oscale = 64
    gemm_mma<2>(g_oh, g_ol, Bh, out, DM, bm, nt * 128, nullptr, nullptr, OSCALE);
}

// ---------------- round fp32 x -> fp16 ----------------
__global__ __launch_bounds__(256) void split_kernel(const float* __restrict__ in) {
    size_t i = ((size_t)blockIdx.x * 256 + threadIdx.x) * 4;
    float4 v = *reinterpret_cast<const float4*>(in + i);
    __half2 h0 = __half2(__float2half(v.x), __float2half(v.y));
    __half2 h1 = __half2(__float2half(v.z), __float2half(v.w));
    *reinterpret_cast<__half2*>(g_xh + i)     = h0;
    *reinterpret_cast<__half2*>(g_xh + i + 2) = h1;
}

// weights: fp32 [K=1024, N=1024] -> transposed fp16 [N, K]; 2 weights/launch
__global__ __launch_bounds__(256) void wsplit2_kernel(const float* __restrict__ WA,
                                                      const float* __restrict__ WB,
                                                      int wbase) {
    const float* W = (blockIdx.z == 0) ? WA : WB;
    const int widx = wbase + blockIdx.z;
    __shared__ float t[32][33];
    const int bx = blockIdx.x * 32;   // n
    const int by = blockIdx.y * 32;   // k
    const int tx = threadIdx.x & 31, ty = threadIdx.x >> 5;
#pragma unroll
    for (int r = 0; r < 32; r += 8)
        t[ty + r][tx] = W[(size_t)(by + ty + r) * 1024 + bx + tx];
    __syncthreads();
    __half* oh = g_wh + ((size_t)widx << 20);
#pragma unroll
    for (int r = 0; r < 32; r += 8) {
        float v = t[tx][ty + r];                          // = W[by+tx][bx+ty+r]
        size_t oi = (size_t)(bx + ty + r) * 1024 + by + tx;
        oh[oi] = __float2half(v);
    }
}

// ---------------- exclusive cumsum of a along time (two-pass) ----------------
__global__ __launch_bounds__(256) void chunksum_kernel() {
    int gid = blockIdx.x * 256 + threadIdx.x;
    int col = gid % QAB;
    int c   = (gid / QAB) % NC;
    int b   = gid / (QAB * NC);
    const float* p = g_a + (size_t)(b * Tt + c * CH) * QAB + col;
    float s = 0.f;
#pragma unroll 8
    for (int r = 0; r < CH; r++) s += p[(size_t)r * QAB];
    g_cs[(b * NC + c) * QAB + col] = s;
}

__global__ __launch_bounds__(256) void excl_kernel() {
    int gid = blockIdx.x * 256 + threadIdx.x;
    int col = gid % QAB;
    int c   = (gid / QAB) % NC;
    int b   = gid / (QAB * NC);
    float off = 0.f;
    for (int cc = 0; cc < c; cc++) off += g_cs[(b * NC + cc) * QAB + col];
    const float* pa = g_a   + (size_t)(b * Tt + c * CH) * QAB + col;
    float*       pe = g_aex + (size_t)(b * Tt + c * CH) * QAB + col;
    float run = off;
#pragma unroll 8
    for (int r = 0; r < CH; r++) {
        pe[(size_t)r * QAB] = run;
        run += pa[(size_t)r * QAB];
    }
}

// -------- per-chunk outer product, stored transposed: P^T[e][d] = sum_t B[t][e] Aex[t][d]
__global__ __launch_bounds__(256) void chunkP_kernel() {
    int c = blockIdx.x & (NC - 1);
    int h = (blockIdx.x >> 5) & (Hh - 1);
    int b = blockIdx.x >> 9;
    __shared__ float Ax[64][64];
    __shared__ float Bx[64][64];
    int tid = threadIdx.x;
    size_t base = (size_t)(b * Tt + c * CH) * QAB + h * Dd;
    for (int idx = tid; idx < 4096; idx += 256) {
        int t = idx >> 6, d = idx & 63;
        Ax[t][d] = g_aex[base + (size_t)t * QAB + d];
        Bx[t][d] = g_b [base + (size_t)t * QAB + d];
    }
    __syncthreads();
    int dr = (tid >> 4) * 4, ec = (tid & 15) * 4;
    float acc[4][4] = {};
#pragma unroll 4
    for (int t = 0; t < 64; t++) {
        float av[4], bv[4];
#pragma unroll
        for (int i = 0; i < 4; i++) av[i] = Ax[t][dr + i];
#pragma unroll
        for (int j = 0; j < 4; j++) bv[j] = Bx[t][ec + j];
#pragma unroll
        for (int i = 0; i < 4; i++)
#pragma unroll
            for (int j = 0; j < 4; j++)
                acc[i][j] = fmaf(av[i], bv[j], acc[i][j]);
    }
    size_t pb = ((size_t)((b * Hh + h) * NC + c)) * 4096;
#pragma unroll
    for (int j = 0; j < 4; j++) {       // transposed store: row e, col d
        float4 v = make_float4(acc[0][j], acc[1][j], acc[2][j], acc[3][j]);
        *reinterpret_cast<float4*>(g_P + pb + (size_t)(ec + j) * 64 + dr) = v;
    }
}

// ---------------- elementwise exclusive scan of P^T over chunks -> M^T -------
__global__ __launch_bounds__(256) void scanM_kernel() {
    int gid = blockIdx.x * 256 + threadIdx.x;
    int de = gid & 4095;
    int bh = gid >> 12;
    size_t base = (size_t)bh * NC * 4096 + de;
    float run = 0.f;
#pragma unroll
    for (int c = 0; c < NC; c++) {
        g_M[base + (size_t)c * 4096] = run;
        run += g_P[base + (size_t)c * 4096];
    }
}

// ---------------- chunk attention via HMMA (bf16 3-term internals) -----------
// S = tril(Q Aex^T);  O = Q M^T_rows + S B^T_rows;  output -> (o/64) fp16 splits
#define OQ_H 0
#define OQ_L 8192
#define OA_H 16384
#define OA_L 24576
#define OB_H 32768
#define OB_L 40960
#define OM_H 49152
#define OM_L 57344
#define ATT_SMEM 65536

__global__ __launch_bounds__(128, 1) void attn_kernel() {
    extern __shared__ char smem[];
    const uint32_t sb = smem_u32(smem);
    int c = blockIdx.x & (NC - 1);
    int h = (blockIdx.x >> 5) & (Hh - 1);
    int b = blockIdx.x >> 9;
    int tid = threadIdx.x, wid = tid >> 5, lane = tid & 31;
    size_t base  = (size_t)(b * Tt + c * CH) * QAB + h * Dd;
    size_t mbase = ((size_t)((b * Hh + h) * NC + c)) * 4096;

    // load + convert to split bf16 smem (SW128 rows of 128B)
    for (int idx = tid; idx < 4096; idx += 128) {
        int t = idx >> 6, d = idx & 63;
        size_t go = base + (size_t)t * QAB + d;
        float q  = g_q[go];
        float a  = g_aex[go];
        float bv = g_b[go];
        float m  = g_M[mbase + idx];                       // row e=t, col d (M^T)
        uint32_t offr = SMEM_SWIZZLE_128B((uint32_t)(t * 128 + d * 2));
        uint32_t offt = SMEM_SWIZZLE_128B((uint32_t)(d * 128 + t * 2));  // B transposed
        __nv_bfloat16 hh, ll;
        hh = __float2bfloat16(q);  ll = __float2bfloat16(q - __bfloat162float(hh));
        *(__nv_bfloat16*)(smem + OQ_H + offr) = hh;
        *(__nv_bfloat16*)(smem + OQ_L + offr) = ll;
        hh = __float2bfloat16(a);  ll = __float2bfloat16(a - __bfloat162float(hh));
        *(__nv_bfloat16*)(smem + OA_H + offr) = hh;
        *(__nv_bfloat16*)(smem + OA_L + offr) = ll;
        hh = __float2bfloat16(bv); ll = __float2bfloat16(bv - __bfloat162float(hh));
        *(__nv_bfloat16*)(smem + OB_H + offt) = hh;
        *(__nv_bfloat16*)(smem + OB_L + offt) = ll;
        hh = __float2bfloat16(m);  ll = __float2bfloat16(m - __bfloat162float(hh));
        *(__nv_bfloat16*)(smem + OM_H + offr) = hh;
        *(__nv_bfloat16*)(smem + OM_L + offr) = ll;
    }
    __syncthreads();

    const int m0 = wid * 16;
    const int ar = lane & 15, ac16 = lane >> 4;
    const int bsub = lane >> 3, br8 = lane & 7;
    const int brow = ((bsub & 1) ? 8 : 0) + br8;
    const int bcsel = (bsub >> 1) ? 16 : 0;
    const int r4 = lane >> 2, c2 = (lane & 3) * 2;

    // ---- gemm1: S = Q @ Aex^T ----
    float sacc[8][4];
#pragma unroll
    for (int j = 0; j < 8; j++)
#pragma unroll
        for (int k = 0; k < 4; k++) sacc[j][k] = 0.f;
#pragma unroll
    for (int t = 0; t < 4; t++) {
        uint32_t qh[4], ql[4], bh_[4][4], bl_[4][4];
        uint32_t aoff = SMEM_SWIZZLE_128B((uint32_t)((m0 + ar) * 128 + t * 32 + ac16 * 16));
        ldsm4(qh, sb + OQ_H + aoff);
        ldsm4(ql, sb + OQ_L + aoff);
#pragma unroll
        for (int g = 0; g < 4; g++) {
            uint32_t boff = SMEM_SWIZZLE_128B((uint32_t)((g * 16 + brow) * 128 + t * 32 + bcsel));
            ldsm4(bh_[g], sb + OA_H + boff);
            ldsm4(bl_[g], sb + OA_L + boff);
        }
#pragma unroll
        for (int nj = 0; nj < 8; nj++) {
            int g = nj >> 1, s2 = nj & 1;
            mma16816b(sacc[nj], qh, bh_[g][s2], bh_[g][s2 + 2]);
            mma16816b(sacc[nj], qh, bl_[g][s2], bl_[g][s2 + 2]);
            mma16816b(sacc[nj], ql, bh_[g][s2], bh_[g][s2 + 2]);
        }
    }

    // causal mask (keep s <= t)
    const int row0 = m0 + r4, row1 = row0 + 8;
#pragma unroll
    for (int nj = 0; nj < 8; nj++) {
        int col = nj * 8 + c2;
        if (col     > row0) sacc[nj][0] = 0.f;
        if (col + 1 > row0) sacc[nj][1] = 0.f;
        if (col     > row1) sacc[nj][2] = 0.f;
        if (col + 1 > row1) sacc[nj][3] = 0.f;
    }

    // S C-frags -> A-frags (hi/lo bf16), pure register repack
    uint32_t sh[4][4], sl[4][4];
#pragma unroll
    for (int j = 0; j < 4; j++) {
        split2b(sacc[2 * j][0],     sacc[2 * j][1],     sh[j][0], sl[j][0]);
        split2b(sacc[2 * j][2],     sacc[2 * j][3],     sh[j][1], sl[j][1]);
        split2b(sacc[2 * j + 1][0], sacc[2 * j + 1][1], sh[j][2], sl[j][2]);
        split2b(sacc[2 * j + 1][2], sacc[2 * j + 1][3], sh[j][3], sl[j][3]);
    }

    // ---- gemm2: O = Q @ M^T  (+ gemm3: O += S @ B^T) ----
    float oacc[8][4];
#pragma unroll
    for (int j = 0; j < 8; j++)
#pragma unroll
        for (int k = 0; k < 4; k++) oacc[j][k] = 0.f;
#pragma unroll
    for (int t = 0; t < 4; t++) {
        uint32_t qh[4], ql[4], bh_[4][4], bl_[4][4];
        uint32_t aoff = SMEM_SWIZZLE_128B((uint32_t)((m0 + ar) * 128 + t * 32 + ac16 * 16));
        ldsm4(qh, sb + OQ_H + aoff);
        ldsm4(ql, sb + OQ_L + aoff);
#pragma unroll
        for (int g = 0; g < 4; g++) {
            uint32_t boff = SMEM_SWIZZLE_128B((uint32_t)((g * 16 + brow) * 128 + t * 32 + bcsel));
            ldsm4(bh_[g], sb + OM_H + boff);
            ldsm4(bl_[g], sb + OM_L + boff);
        }
#pragma unroll
        for (int nj = 0; nj < 8; nj++) {
            int g = nj >> 1, s2 = nj & 1;
            mma16816b(oacc[nj], qh, bh_[g][s2], bh_[g][s2 + 2]);
            mma16816b(oacc[nj], qh, bl_[g][s2], bl_[g][s2 + 2]);
            mma16816b(oacc[nj], ql, bh_[g][s2], bh_[g][s2 + 2]);
        }
    }
#pragma unroll
    for (int j = 0; j < 4; j++) {              // k-tile over s = 16j..16j+15
        uint32_t bh_[4][4], bl_[4][4];
#pragma unroll
        for (int g = 0; g < 4; g++) {
            uint32_t boff = SMEM_SWIZZLE_128B((uint32_t)((g * 16 + brow) * 128 + j * 32 + bcsel));
            ldsm4(bh_[g], sb + OB_H + boff);
            ldsm4(bl_[g], sb + OB_L + boff);
        }
#pragma unroll
        for (int nj = 0; nj < 8; nj++) {
            int g = nj >> 1, s2 = nj & 1;
            mma16816b(oacc[nj], sh[j], bh_[g][s2], bh_[g][s2 + 2]);
            mma16816b(oacc[nj], sh[j], bl_[g][s2], bl_[g][s2 + 2]);
            mma16816b(oacc[nj], sl[j], bh_[g][s2], bh_[g][s2 + 2]);
        }
    }

    // epilogue: (o/64) fp32 -> fp16 hi/lo gmem (fp16-safe after scaling)
#pragma unroll
    for (int nj = 0; nj < 8; nj++) {
        int col = nj * 8 + c2;
        uint32_t h0, l0, h1, l1;
        split2h(oacc[nj][0] * ISCALE, oacc[nj][1] * ISCALE, h0, l0);
        split2h(oacc[nj][2] * ISCALE, oacc[nj][3] * ISCALE, h1, l1);
        size_t r0o = base + (size_t)row0 * QAB + col;
        size_t r1o = base + (size_t)row1 * QAB + col;
        *reinterpret_cast<uint32_t*>(g_oh + r0o) = h0;
        *reinterpret_cast<uint32_t*>(g_ol + r0o) = l0;
        *reinterpret_cast<uint32_t*>(g_oh + r1o) = h1;
        *reinterpret_cast<uint32_t*>(g_ol + r1o) = l1;
    }
}

// ---------------- launcher ----------------
extern "C" void kernel_launch(void* const* d_in, const int* in_sizes, int n_in,
                              void* d_out, int out_size) {
    const float* x  = (const float*)d_in[0];
    const float* Wq = (const float*)d_in[1];
    const float* Wa = (const float*)d_in[2];
    const float* Wb = (const float*)d_in[3];
    const float* Wo = (const float*)d_in[4];
    const float* qg = (const float*)d_in[5];
    const float* qb = (const float*)d_in[6];
    const float* ag = (const float*)d_in[7];
    const float* ab = (const float*)d_in[8];
    const float* bg = (const float*)d_in[9];
    const float* bbv = (const float*)d_in[10];
    float* out = (float*)d_out;

    cudaFuncSetAttribute(proj_tc_kernel, cudaFuncAttributeMaxDynamicSharedMemorySize, GM_SMEM_1);
    cudaFuncSetAttribute(out_tc_kernel,  cudaFuncAttributeMaxDynamicSharedMemorySize, GM_SMEM_2);
    cudaFuncSetAttribute(attn_kernel,    cudaFuncAttributeMaxDynamicSharedMemorySize, ATT_SMEM);

    split_kernel<<<4096, 256>>>(x);                              // launch 0
    wsplit2_kernel<<<dim3(32, 32, 2), 256>>>(Wq, Wa, 0);         // launch 1
    wsplit2_kernel<<<dim3(32, 32, 2), 256>>>(Wb, Wo, 2);         // launch 2

    proj_tc_kernel<<<dim3(24, 32), 512, GM_SMEM_1>>>(qg, qb, ag, ab, bg, bbv);  // launch 3 (profiled)

    chunksum_kernel<<<(Bb * QAB * NC) / 256, 256>>>();
    excl_kernel<<<(Bb * QAB * NC) / 256, 256>>>();

    chunkP_kernel<<<Bb * Hh * NC, 256>>>();
    scanM_kernel<<<(Bb * Hh * 4096) / 256, 256>>>();
    attn_kernel<<<Bb * Hh * NC, 128, ATT_SMEM>>>();

    out_tc_kernel<<<dim3(8, 32), 512, GM_SMEM_2>>>(out);
}

// round 14
// speedup vs baseline: 1.7092x; 1.0532x over previous
#include <cuda_runtime.h>
#include <cuda_fp16.h>
#include <cuda_bf16.h>
#include <cstdint>

#define Bb   2
#define Tt   2048
#define DM   1024
#define Hh   16
#define Dd   64
#define BT   4096          // B*T
#define QAB  1024          // H*D
#define CH   64            // chunk length
#define NC   32            // T / CH

#define OSCALE 64.0f
#define ISCALE (1.0f / 64.0f)

// ---------------- scratch (device globals; no allocs allowed) ----------------
__device__ float g_q  [BT * QAB];
__device__ float g_a  [BT * QAB];
__device__ float g_b  [BT * QAB];
__device__ float g_aex[BT * QAB];
__device__ float g_P  [Bb * Hh * NC * Dd * Dd];   // stored TRANSPOSED: [e][d]
__device__ float g_M  [Bb * Hh * NC * Dd * Dd];   // exclusive scan of P^T = M^T
__device__ float g_cs [Bb * QAB * NC];

// fp16 operands
__device__ __half g_xh[BT * DM];      // x rounded (1-term proj)
__device__ __half g_oh[BT * QAB];     // o/64 hi
__device__ __half g_ol[BT * QAB];     // o/64 lo (2-term out GEMM)
__device__ __half g_wh[4u << 20];     // 4 weights, each [N=1024][K=1024] (transposed)

// ================= helpers ==================
__device__ __forceinline__ uint32_t smem_u32(const void* p) {
    uint32_t a;
    asm("{ .reg .u64 t; cvta.to.shared.u64 t, %1; cvt.u32.u64 %0, t; }" : "=r"(a) : "l"(p));
    return a;
}
#define SMEM_SWIZZLE_128B(off) ((off) ^ (((off) >> 3) & 0x70))

__device__ __forceinline__ void cp16(uint32_t dst, const void* src) {
    asm volatile("cp.async.cg.shared.global [%0], [%1], 16;" :: "r"(dst), "l"(src));
}
#define CP_COMMIT() asm volatile("cp.async.commit_group;" ::: "memory")

__device__ __forceinline__ void ldsm4(uint32_t* r, uint32_t a) {
    asm volatile("ldmatrix.sync.aligned.m8n8.x4.shared.b16 {%0,%1,%2,%3}, [%4];"
                 : "=r"(r[0]), "=r"(r[1]), "=r"(r[2]), "=r"(r[3]) : "r"(a));
}

__device__ __forceinline__ void mma16816h(float* c, const uint32_t* a,
                                          uint32_t b0, uint32_t b1) {
    asm volatile(
        "mma.sync.aligned.m16n8k16.row.col.f32.f16.f16.f32 "
        "{%0,%1,%2,%3}, {%4,%5,%6,%7}, {%8,%9}, {%0,%1,%2,%3};"
        : "+f"(c[0]), "+f"(c[1]), "+f"(c[2]), "+f"(c[3])
        : "r"(a[0]), "r"(a[1]), "r"(a[2]), "r"(a[3]), "r"(b0), "r"(b1));
}

__device__ __forceinline__ void mma16816b(float* c, const uint32_t* a,
                                          uint32_t b0, uint32_t b1) {
    asm volatile(
        "mma.sync.aligned.m16n8k16.row.col.f32.bf16.bf16.f32 "
        "{%0,%1,%2,%3}, {%4,%5,%6,%7}, {%8,%9}, {%0,%1,%2,%3};"
        : "+f"(c[0]), "+f"(c[1]), "+f"(c[2]), "+f"(c[3])
        : "r"(a[0]), "r"(a[1]), "r"(a[2]), "r"(a[3]), "r"(b0), "r"(b1));
}

// pack two fp32 into fp16x2 hi/lo splits
__device__ __forceinline__ void split2h(float x, float y, uint32_t& hi, uint32_t& lo) {
    __half hx = __float2half(x), hy = __float2half(y);
    float rx = x - __half2float(hx), ry = y - __half2float(hy);
    __half lx = __float2half(rx), ly = __float2half(ry);
    hi = ((uint32_t)__half_as_ushort(hy) << 16) | (uint32_t)__half_as_ushort(hx);
    lo = ((uint32_t)__half_as_ushort(ly) << 16) | (uint32_t)__half_as_ushort(lx);
}
// pack two fp32 into bf16x2 hi/lo splits
__device__ __forceinline__ void split2b(float x, float y, uint32_t& hi, uint32_t& lo) {
    __nv_bfloat16 hx = __float2bfloat16(x), hy = __float2bfloat16(y);
    float rx = x - __bfloat162float(hx), ry = y - __bfloat162float(hy);
    __nv_bfloat16 lx = __float2bfloat16(rx), ly = __float2bfloat16(ry);
    hi = ((uint32_t)__bfloat16_as_ushort(hy) << 16) | (uint32_t)__bfloat16_as_ushort(hx);
    lo = ((uint32_t)__bfloat16_as_ushort(ly) << 16) | (uint32_t)__bfloat16_as_ushort(lx);
}

// ================= HMMA GEMM: C = oscale*(A fp16 [1 or 2 term]) @ Wh^T ======
// 256 threads, warp grid 4(M) x 2(N), warp tile 32x64 (fat tile: low smem traffic).
// TERMS=1: stage 32KB, ring 96KB -> 2 CTAs/SM. TERMS=2: stage 48KB, 1 CTA/SM.
template <int TERMS>
__device__ __forceinline__ void gemm_mma(const __half* __restrict__ Ah,
                                         const __half* __restrict__ Al,
                                         const __half* __restrict__ Bh,
                                         float* __restrict__ C, int ldc,
                                         int bm, int bn,
                                         const float* __restrict__ gamma,
                                         const float* __restrict__ beta,
                                         float oscale) {
    constexpr int NTILES = TERMS + 1;          // A tiles + B tile
    constexpr uint32_t STAGE = NTILES * 16384;
    extern __shared__ char smem[];
    const uint32_t sb = smem_u32(smem);
    const int tid = threadIdx.x, wid = tid >> 5, lane = tid & 31;
    const int m0 = (wid >> 1) * 32;     // warp row base (4 rows of warps)
    const int n0 = (wid & 1) * 64;      // warp col base (2 cols of warps)

    float acc[2][8][4];
#pragma unroll
    for (int i = 0; i < 2; i++)
#pragma unroll
        for (int j = 0; j < 8; j++)
#pragma unroll
            for (int k = 0; k < 4; k++) acc[i][j][k] = 0.f;

    auto load_stage = [&](int st, int k0) {
        uint32_t base = sb + st * STAGE;
#pragma unroll
        for (int tile = 0; tile < NTILES; tile++) {
            const __half* src = (tile == 0) ? Ah
                              : (TERMS == 2 && tile == 1) ? Al : Bh;
            const int rb = (tile < NTILES - 1) ? bm : bn;
#pragma unroll
            for (int s = tid; s < 1024; s += 256) {
                int row = s >> 3, ks = s & 7;
                uint32_t dst = base + tile * 16384 +
                               SMEM_SWIZZLE_128B((uint32_t)(row * 128 + ks * 16));
                cp16(dst, src + (size_t)(rb + row) * 1024 + k0 + ks * 8);
            }
        }
        CP_COMMIT();
    };

    const int ar  = lane & 15, ac16 = lane >> 4;             // A 16x16
    const int bsub = lane >> 3, br8 = lane & 7;              // B 16x16
    const int brow = ((bsub & 1) ? 8 : 0) + br8;
    const int bcsel = (bsub >> 1) ? 16 : 0;

    // hoist swizzled intra-stage offsets out of the main loop
    uint32_t aoffs[4][2], boffs[4][4];
#pragma unroll
    for (int t = 0; t < 4; t++) {
#pragma unroll
        for (int mi = 0; mi < 2; mi++)
            aoffs[t][mi] = SMEM_SWIZZLE_128B(
                (uint32_t)((m0 + mi * 16 + ar) * 128 + t * 32 + ac16 * 16));
#pragma unroll
        for (int g = 0; g < 4; g++)
            boffs[t][g] = SMEM_SWIZZLE_128B(
                (uint32_t)((n0 + g * 16 + brow) * 128 + t * 32 + bcsel));
    }

    load_stage(0, 0);       // chunk 0 -> buf 0
    load_stage(1, 64);      // chunk 1 -> buf 1
    for (int i = 0; i < 16; i++) {
        asm volatile("cp.async.wait_group 1;" ::: "memory");   // chunk-i groups done
        __syncthreads();                                       // buf i%3 valid CTA-wide

        if (i < 14) load_stage((i + 2) % 3, (i + 2) * 64);     // prefetch, overlaps MMA
        else CP_COMMIT();                  // empty group keeps wait_group counts aligned

        const uint32_t ahb = sb + (i % 3) * STAGE;
        const uint32_t alb = ahb + 16384;                      // valid when TERMS==2
        const uint32_t bhb = ahb + (NTILES - 1) * 16384;

#pragma unroll
        for (int t = 0; t < 4; t++) {
            uint32_t ahf[2][4], alf[2][4], bhf[4][4];
#pragma unroll
            for (int mi = 0; mi < 2; mi++) {
                ldsm4(ahf[mi], ahb + aoffs[t][mi]);
                if (TERMS == 2) ldsm4(alf[mi], alb + aoffs[t][mi]);
            }
#pragma unroll
            for (int g = 0; g < 4; g++)
                ldsm4(bhf[g], bhb + boffs[t][g]);
#pragma unroll
            for (int mi = 0; mi < 2; mi++)
#pragma unroll
                for (int nj = 0; nj < 8; nj++) {
                    int g = nj >> 1, s2 = nj & 1;
                    mma16816h(acc[mi][nj], ahf[mi], bhf[g][s2], bhf[g][s2 + 2]);
                    if (TERMS == 2)
                        mma16816h(acc[mi][nj], alf[mi], bhf[g][s2], bhf[g][s2 + 2]);
                }
        }
    }

    const int r4 = lane >> 2, c2 = (lane & 3) * 2;

    // -------- fused per-head LayerNorm (head == warp's 64-col span) --------
    if (gamma) {
        float gv[16], bv[16];
#pragma unroll
        for (int nj = 0; nj < 8; nj++)
#pragma unroll
            for (int t = 0; t < 2; t++) {
                int d = nj * 8 + c2 + t;
                gv[nj * 2 + t] = __ldg(gamma + d);
                bv[nj * 2 + t] = __ldg(beta + d);
            }
#pragma unroll
        for (int mi = 0; mi < 2; mi++) {
            float s0 = 0.f, q0 = 0.f, s1 = 0.f, q1 = 0.f;
#pragma unroll
            for (int nj = 0; nj < 8; nj++) {
                float v0 = acc[mi][nj][0], v1 = acc[mi][nj][1];
                float v2 = acc[mi][nj][2], v3 = acc[mi][nj][3];
                s0 += v0 + v1; q0 += v0 * v0 + v1 * v1;
                s1 += v2 + v3; q1 += v2 * v2 + v3 * v3;
            }
#pragma unroll
            for (int o = 1; o <= 2; o <<= 1) {
                s0 += __shfl_xor_sync(0xFFFFFFFFu, s0, o);
                q0 += __shfl_xor_sync(0xFFFFFFFFu, q0, o);
                s1 += __shfl_xor_sync(0xFFFFFFFFu, s1, o);
                q1 += __shfl_xor_sync(0xFFFFFFFFu, q1, o);
            }
            float m0s = s0 * (1.f / 64.f);
            float r0 = rsqrtf(q0 * (1.f / 64.f) - m0s * m0s + 1e-5f);
            float m1s = s1 * (1.f / 64.f);
            float r1 = rsqrtf(q1 * (1.f / 64.f) - m1s * m1s + 1e-5f);
#pragma unroll
            for (int nj = 0; nj < 8; nj++) {
                acc[mi][nj][0] = (acc[mi][nj][0] - m0s) * r0 * gv[nj * 2]     + bv[nj * 2];
                acc[mi][nj][1] = (acc[mi][nj][1] - m0s) * r0 * gv[nj * 2 + 1] + bv[nj * 2 + 1];
                acc[mi][nj][2] = (acc[mi][nj][2] - m1s) * r1 * gv[nj * 2]     + bv[nj * 2];
                acc[mi][nj][3] = (acc[mi][nj][3] - m1s) * r1 * gv[nj * 2 + 1] + bv[nj * 2 + 1];
            }
        }
    }

    // epilogue: c frag * oscale -> gmem fp32
#pragma unroll
    for (int mi = 0; mi < 2; mi++)
#pragma unroll
        for (int nj = 0; nj < 8; nj++) {
            int m = bm + m0 + mi * 16 + r4;
            int n = bn + n0 + nj * 8 + c2;
            float2 v0 = make_float2(acc[mi][nj][0] * oscale, acc[mi][nj][1] * oscale);
            float2 v1 = make_float2(acc[mi][nj][2] * oscale, acc[mi][nj][3] * oscale);
            *reinterpret_cast<float2*>(C + (size_t)m * ldc + n) = v0;
            *reinterpret_cast<float2*>(C + (size_t)(m + 8) * ldc + n) = v1;
        }
}

#define GM_SMEM_1 (3 * 32768)
#define GM_SMEM_2 (3 * 49152)

__global__ __launch_bounds__(256, 2) void proj_tc_kernel(const float* __restrict__ qg,
                                                         const float* __restrict__ qb,
                                                         const float* __restrict__ ag,
                                                         const float* __restrict__ ab,
                                                         const float* __restrict__ bg,
                                                         const float* __restrict__ bbv) {
    const int w = blockIdx.x >> 3, nt = blockIdx.x & 7, bm = blockIdx.y * 128;
    const __half* Bh = g_wh + ((size_t)w << 20);
    float* C;
    const float* gm;
    const float* bt;
    if (w == 0)      { C = g_q; gm = qg; bt = qb; }
    else if (w == 1) { C = g_a; gm = ag; bt = ab; }
    else             { C = g_b; gm = bg; bt = bbv; }
    gemm_mma<1>(g_xh, nullptr, Bh, C, QAB, bm, nt * 128, gm, bt, 1.0f);
}

__global__ __launch_bounds__(256, 1) void out_tc_kernel(float* __restrict__ out) {
    const int nt = blockIdx.x, bm = blockIdx.y * 128;
    const __half* Bh = g_wh + ((size_t)3 << 20);
    // A-side holds o/64 exact (hi+lo); restore with oscale = 64
    gemm_mma<2>(g_oh, g_ol, Bh, out, DM, bm, nt * 128, nullptr, nullptr, OSCALE);
}

// ---------------- round fp32 x -> fp16 ----------------
__global__ __launch_bounds__(256) void split_kernel(const float* __restrict__ in) {
    size_t i = ((size_t)blockIdx.x * 256 + threadIdx.x) * 4;
    float4 v = *reinterpret_cast<const float4*>(in + i);
    __half2 h0 = __half2(__float2half(v.x), __float2half(v.y));
    __half2 h1 = __half2(__float2half(v.z), __float2half(v.w));
    *reinterpret_cast<__half2*>(g_xh + i)     = h0;
    *reinterpret_cast<__half2*>(g_xh + i + 2) = h1;
}

// weights: fp32 [K=1024, N=1024] -> transposed fp16 [N, K]; 2 weights/launch
__global__ __launch_bounds__(256) void wsplit2_kernel(const float* __restrict__ WA,
                                                      const float* __restrict__ WB,
                                                      int wbase) {
    const float* W = (blockIdx.z == 0) ? WA : WB;
    const int widx = wbase + blockIdx.z;
    __shared__ float t[32][33];
    const int bx = blockIdx.x * 32;   // n
    const int by = blockIdx.y * 32;   // k
    const int tx = threadIdx.x & 31, ty = threadIdx.x >> 5;
#pragma unroll
    for (int r = 0; r < 32; r += 8)
        t[ty + r][tx] = W[(size_t)(by + ty + r) * 1024 + bx + tx];
    __syncthreads();
    __half* oh = g_wh + ((size_t)widx << 20);
#pragma unroll
    for (int r = 0; r < 32; r += 8) {
        float v = t[tx][ty + r];                          // = W[by+tx][bx+ty+r]
        size_t oi = (size_t)(bx + ty + r) * 1024 + by + tx;
        oh[oi] = __float2half(v);
    }
}

// ---------------- exclusive cumsum of a along time (two-pass) ----------------
__global__ __launch_bounds__(256) void chunksum_kernel() {
    int gid = blockIdx.x * 256 + threadIdx.x;
    int col = gid % QAB;
    int c   = (gid / QAB) % NC;
    int b   = gid / (QAB * NC);
    const float* p = g_a + (size_t)(b * Tt + c * CH) * QAB + col;
    float s = 0.f;
#pragma unroll 8
    for (int r = 0; r < CH; r++) s += p[(size_t)r * QAB];
    g_cs[(b * NC + c) * QAB + col] = s;
}

__global__ __launch_bounds__(256) void excl_kernel() {
    int gid = blockIdx.x * 256 + threadIdx.x;
    int col = gid % QAB;
    int c   = (gid / QAB) % NC;
    int b   = gid / (QAB * NC);
    float off = 0.f;
    for (int cc = 0; cc < c; cc++) off += g_cs[(b * NC + cc) * QAB + col];
    const float* pa = g_a   + (size_t)(b * Tt + c * CH) * QAB + col;
    float*       pe = g_aex + (size_t)(b * Tt + c * CH) * QAB + col;
    float run = off;
#pragma unroll 8
    for (int r = 0; r < CH; r++) {
        pe[(size_t)r * QAB] = run;
        run += pa[(size_t)r * QAB];
    }
}

// -------- per-chunk outer product, stored transposed: P^T[e][d] = sum_t B[t][e] Aex[t][d]
__global__ __launch_bounds__(256) void chunkP_kernel() {
    int c = blockIdx.x & (NC - 1);
    int h = (blockIdx.x >> 5) & (Hh - 1);
    int b = blockIdx.x >> 9;
    __shared__ float Ax[64][64];
    __shared__ float Bx[64][64];
    int tid = threadIdx.x;
    size_t base = (size_t)(b * Tt + c * CH) * QAB + h * Dd;
    for (int idx = tid; idx < 4096; idx += 256) {
        int t = idx >> 6, d = idx & 63;
        Ax[t][d] = g_aex[base + (size_t)t * QAB + d];
        Bx[t][d] = g_b [base + (size_t)t * QAB + d];
    }
    __syncthreads();
    int dr = (tid >> 4) * 4, ec = (tid & 15) * 4;
    float acc[4][4] = {};
#pragma unroll 4
    for (int t = 0; t < 64; t++) {
        float av[4], bv[4];
#pragma unroll
        for (int i = 0; i < 4; i++) av[i] = Ax[t][dr + i];
#pragma unroll
        for (int j = 0; j < 4; j++) bv[j] = Bx[t][ec + j];
#pragma unroll
        for (int i = 0; i < 4; i++)
#pragma unroll
            for (int j = 0; j < 4; j++)
                acc[i][j] = fmaf(av[i], bv[j], acc[i][j]);
    }
    size_t pb = ((size_t)((b * Hh + h) * NC + c)) * 4096;
#pragma unroll
    for (int j = 0; j < 4; j++) {       // transposed store: row e, col d
        float4 v = make_float4(acc[0][j], acc[1][j], acc[2][j], acc[3][j]);
        *reinterpret_cast<float4*>(g_P + pb + (size_t)(ec + j) * 64 + dr) = v;
    }
}

// ---------------- elementwise exclusive scan of P^T over chunks -> M^T -------
__global__ __launch_bounds__(256) void scanM_kernel() {
    int gid = blockIdx.x * 256 + threadIdx.x;
    int de = gid & 4095;
    int bh = gid >> 12;
    size_t base = (size_t)bh * NC * 4096 + de;
    float run = 0.f;
#pragma unroll
    for (int c = 0; c < NC; c++) {
        g_M[base + (size_t)c * 4096] = run;
        run += g_P[base + (size_t)c * 4096];
    }
}

// ---------------- chunk attention via HMMA (bf16 3-term internals) -----------
// S = tril(Q Aex^T);  O = Q M^T_rows + S B^T_rows;  output -> (o/64) fp16 splits
#define OQ_H 0
#define OQ_L 8192
#define OA_H 16384
#define OA_L 24576
#define OB_H 32768
#define OB_L 40960
#define OM_H 49152
#define OM_L 57344
#define ATT_SMEM 65536

__global__ __launch_bounds__(128, 1) void attn_kernel() {
    extern __shared__ char smem[];
    const uint32_t sb = smem_u32(smem);
    int c = blockIdx.x & (NC - 1);
    int h = (blockIdx.x >> 5) & (Hh - 1);
    int b = blockIdx.x >> 9;
    int tid = threadIdx.x, wid = tid >> 5, lane = tid & 31;
    size_t base  = (size_t)(b * Tt + c * CH) * QAB + h * Dd;
    size_t mbase = ((size_t)((b * Hh + h) * NC + c)) * 4096;

    // load + convert to split bf16 smem (SW128 rows of 128B)
    for (int idx = tid; idx < 4096; idx += 128) {
        int t = idx >> 6, d = idx & 63;
        size_t go = base + (size_t)t * QAB + d;
        float q  = g_q[go];
        float a  = g_aex[go];
        float bv = g_b[go];
        float m  = g_M[mbase + idx];                       // row e=t, col d (M^T)
        uint32_t offr = SMEM_SWIZZLE_128B((uint32_t)(t * 128 + d * 2));
        uint32_t offt = SMEM_SWIZZLE_128B((uint32_t)(d * 128 + t * 2));  // B transposed
        __nv_bfloat16 hh, ll;
        hh = __float2bfloat16(q);  ll = __float2bfloat16(q - __bfloat162float(hh));
        *(__nv_bfloat16*)(smem + OQ_H + offr) = hh;
        *(__nv_bfloat16*)(smem + OQ_L + offr) = ll;
        hh = __float2bfloat16(a);  ll = __float2bfloat16(a - __bfloat162float(hh));
        *(__nv_bfloat16*)(smem + OA_H + offr) = hh;
        *(__nv_bfloat16*)(smem + OA_L + offr) = ll;
        hh = __float2bfloat16(bv); ll = __float2bfloat16(bv - __bfloat162float(hh));
        *(__nv_bfloat16*)(smem + OB_H + offt) = hh;
        *(__nv_bfloat16*)(smem + OB_L + offt) = ll;
        hh = __float2bfloat16(m);  ll = __float2bfloat16(m - __bfloat162float(hh));
        *(__nv_bfloat16*)(smem + OM_H + offr) = hh;
        *(__nv_bfloat16*)(smem + OM_L + offr) = ll;
    }
    __syncthreads();

    const int m0 = wid * 16;
    const int ar = lane & 15, ac16 = lane >> 4;
    const int bsub = lane >> 3, br8 = lane & 7;
    const int brow = ((bsub & 1) ? 8 : 0) + br8;
    const int bcsel = (bsub >> 1) ? 16 : 0;
    const int r4 = lane >> 2, c2 = (lane & 3) * 2;

    // ---- gemm1: S = Q @ Aex^T ----
    float sacc[8][4];
#pragma unroll
    for (int j = 0; j < 8; j++)
#pragma unroll
        for (int k = 0; k < 4; k++) sacc[j][k] = 0.f;
#pragma unroll
    for (int t = 0; t < 4; t++) {
        uint32_t qh[4], ql[4], bh_[4][4], bl_[4][4];
        uint32_t aoff = SMEM_SWIZZLE_128B((uint32_t)((m0 + ar) * 128 + t * 32 + ac16 * 16));
        ldsm4(qh, sb + OQ_H + aoff);
        ldsm4(ql, sb + OQ_L + aoff);
#pragma unroll
        for (int g = 0; g < 4; g++) {
            uint32_t boff = SMEM_SWIZZLE_128B((uint32_t)((g * 16 + brow) * 128 + t * 32 + bcsel));
            ldsm4(bh_[g], sb + OA_H + boff);
            ldsm4(bl_[g], sb + OA_L + boff);
        }
#pragma unroll
        for (int nj = 0; nj < 8; nj++) {
            int g = nj >> 1, s2 = nj & 1;
            mma16816b(sacc[nj], qh, bh_[g][s2], bh_[g][s2 + 2]);
            mma16816b(sacc[nj], qh, bl_[g][s2], bl_[g][s2 + 2]);
            mma16816b(sacc[nj], ql, bh_[g][s2], bh_[g][s2 + 2]);
        }
    }

    // causal mask (keep s <= t)
    const int row0 = m0 + r4, row1 = row0 + 8;
#pragma unroll
    for (int nj = 0; nj < 8; nj++) {
        int col = nj * 8 + c2;
        if (col     > row0) sacc[nj][0] = 0.f;
        if (col + 1 > row0) sacc[nj][1] = 0.f;
        if (col     > row1) sacc[nj][2] = 0.f;
        if (col + 1 > row1) sacc[nj][3] = 0.f;
    }

    // S C-frags -> A-frags (hi/lo bf16), pure register repack
    uint32_t sh[4][4], sl[4][4];
#pragma unroll
    for (int j = 0; j < 4; j++) {
        split2b(sacc[2 * j][0],     sacc[2 * j][1],     sh[j][0], sl[j][0]);
        split2b(sacc[2 * j][2],     sacc[2 * j][3],     sh[j][1], sl[j][1]);
        split2b(sacc[2 * j + 1][0], sacc[2 * j + 1][1], sh[j][2], sl[j][2]);
        split2b(sacc[2 * j + 1][2], sacc[2 * j + 1][3], sh[j][3], sl[j][3]);
    }

    // ---- gemm2: O = Q @ M^T  (+ gemm3: O += S @ B^T) ----
    float oacc[8][4];
#pragma unroll
    for (int j = 0; j < 8; j++)
#pragma unroll
        for (int k = 0; k < 4; k++) oacc[j][k] = 0.f;
#pragma unroll
    for (int t = 0; t < 4; t++) {
        uint32_t qh[4], ql[4], bh_[4][4], bl_[4][4];
        uint32_t aoff = SMEM_SWIZZLE_128B((uint32_t)((m0 + ar) * 128 + t * 32 + ac16 * 16));
        ldsm4(qh, sb + OQ_H + aoff);
        ldsm4(ql, sb + OQ_L + aoff);
#pragma unroll
        for (int g = 0; g < 4; g++) {
            uint32_t boff = SMEM_SWIZZLE_128B((uint32_t)((g * 16 + brow) * 128 + t * 32 + bcsel));
            ldsm4(bh_[g], sb + OM_H + boff);
            ldsm4(bl_[g], sb + OM_L + boff);
        }
#pragma unroll
        for (int nj = 0; nj < 8; nj++) {
            int g = nj >> 1, s2 = nj & 1;
            mma16816b(oacc[nj], qh, bh_[g][s2], bh_[g][s2 + 2]);
            mma16816b(oacc[nj], qh, bl_[g][s2], bl_[g][s2 + 2]);
            mma16816b(oacc[nj], ql, bh_[g][s2], bh_[g][s2 + 2]);
        }
    }
#pragma unroll
    for (int j = 0; j < 4; j++) {              // k-tile over s = 16j..16j+15
        uint32_t bh_[4][4], bl_[4][4];
#pragma unroll
        for (int g = 0; g < 4; g++) {
            uint32_t boff = SMEM_SWIZZLE_128B((uint32_t)((g * 16 + brow) * 128 + j * 32 + bcsel));
            ldsm4(bh_[g], sb + OB_H + boff);
            ldsm4(bl_[g], sb + OB_L + boff);
        }
#pragma unroll
        for (int nj = 0; nj < 8; nj++) {
            int g = nj >> 1, s2 = nj & 1;
            mma16816b(oacc[nj], sh[j], bh_[g][s2], bh_[g][s2 + 2]);
            mma16816b(oacc[nj], sh[j], bl_[g][s2], bl_[g][s2 + 2]);
            mma16816b(oacc[nj], sl[j], bh_[g][s2], bh_[g][s2 + 2]);
        }
    }

    // epilogue: (o/64) fp32 -> fp16 hi/lo gmem (fp16-safe after scaling)
#pragma unroll
    for (int nj = 0; nj < 8; nj++) {
        int col = nj * 8 + c2;
        uint32_t h0, l0, h1, l1;
        split2h(oacc[nj][0] * ISCALE, oacc[nj][1] * ISCALE, h0, l0);
        split2h(oacc[nj][2] * ISCALE, oacc[nj][3] * ISCALE, h1, l1);
        size_t r0o = base + (size_t)row0 * QAB + col;
        size_t r1o = base + (size_t)row1 * QAB + col;
        *reinterpret_cast<uint32_t*>(g_oh + r0o) = h0;
        *reinterpret_cast<uint32_t*>(g_ol + r0o) = l0;
        *reinterpret_cast<uint32_t*>(g_oh + r1o) = h1;
        *reinterpret_cast<uint32_t*>(g_ol + r1o) = l1;
    }
}

// ---------------- launcher ----------------
extern "C" void kernel_launch(void* const* d_in, const int* in_sizes, int n_in,
                              void* d_out, int out_size) {
    const float* x  = (const float*)d_in[0];
    const float* Wq = (const float*)d_in[1];
    const float* Wa = (const float*)d_in[2];
    const float* Wb = (const float*)d_in[3];
    const float* Wo = (const float*)d_in[4];
    const float* qg = (const float*)d_in[5];
    const float* qb = (const float*)d_in[6];
    const float* ag = (const float*)d_in[7];
    const float* ab = (const float*)d_in[8];
    const float* bg = (const float*)d_in[9];
    const float* bbv = (const float*)d_in[10];
    float* out = (float*)d_out;

    cudaFuncSetAttribute(proj_tc_kernel, cudaFuncAttributeMaxDynamicSharedMemorySize, GM_SMEM_1);
    cudaFuncSetAttribute(out_tc_kernel,  cudaFuncAttributeMaxDynamicSharedMemorySize, GM_SMEM_2);
    cudaFuncSetAttribute(attn_kernel,    cudaFuncAttributeMaxDynamicSharedMemorySize, ATT_SMEM);

    split_kernel<<<4096, 256>>>(x);                              // launch 0
    wsplit2_kernel<<<dim3(32, 32, 2), 256>>>(Wq, Wa, 0);         // launch 1
    wsplit2_kernel<<<dim3(32, 32, 2), 256>>>(Wb, Wo, 2);         // launch 2

    proj_tc_kernel<<<dim3(24, 32), 256, GM_SMEM_1>>>(qg, qb, ag, ab, bg, bbv);  // launch 3 (profiled)

    chunksum_kernel<<<(Bb * QAB * NC) / 256, 256>>>();
    excl_kernel<<<(Bb * QAB * NC) / 256, 256>>>();

    chunkP_kernel<<<Bb * Hh * NC, 256>>>();
    scanM_kernel<<<(Bb * Hh * 4096) / 256, 256>>>();
    attn_kernel<<<Bb * Hh * NC, 128, ATT_SMEM>>>();

    out_tc_kernel<<<dim3(8, 32), 256, GM_SMEM_2>>>(out);
}

// round 15
// speedup vs baseline: 1.9467x; 1.1390x over previous
#include <cuda_runtime.h>
#include <cuda_fp16.h>
#include <cuda_bf16.h>
#include <cstdint>

#define Bb   2
#define Tt   2048
#define DM   1024
#define Hh   16
#define Dd   64
#define BT   4096          // B*T
#define QAB  1024          // H*D
#define CH   64            // chunk length
#define NC   32            // T / CH

#define OSCALE 64.0f
#define ISCALE (1.0f / 64.0f)

// ---------------- scratch (device globals; no allocs allowed) ----------------
__device__ float g_q  [BT * QAB];
__device__ float g_a  [BT * QAB];
__device__ float g_b  [BT * QAB];
__device__ float g_aex[BT * QAB];
__device__ float g_P  [Bb * Hh * NC * Dd * Dd];   // stored TRANSPOSED: [e][d]
__device__ float g_M  [Bb * Hh * NC * Dd * Dd];   // exclusive scan of P^T = M^T
__device__ float g_cs [Bb * QAB * NC];

// fp16 operands (single-rounded A-sides)
__device__ __half g_xh[BT * DM];      // x rounded (1-term proj)
__device__ __half g_oh[BT * QAB];     // o/64 rounded (1-term out GEMM)
__device__ __half g_wh[4u << 20];     // 4 weights, each [N=1024][K=1024] (transposed)

// ================= helpers ==================
__device__ __forceinline__ uint32_t smem_u32(const void* p) {
    uint32_t a;
    asm("{ .reg .u64 t; cvta.to.shared.u64 t, %1; cvt.u32.u64 %0, t; }" : "=r"(a) : "l"(p));
    return a;
}
#define SMEM_SWIZZLE_128B(off) ((off) ^ (((off) >> 3) & 0x70))

__device__ __forceinline__ void cp16(uint32_t dst, const void* src) {
    asm volatile("cp.async.cg.shared.global [%0], [%1], 16;" :: "r"(dst), "l"(src));
}
#define CP_COMMIT() asm volatile("cp.async.commit_group;" ::: "memory")

__device__ __forceinline__ void ldsm4(uint32_t* r, uint32_t a) {
    asm volatile("ldmatrix.sync.aligned.m8n8.x4.shared.b16 {%0,%1,%2,%3}, [%4];"
                 : "=r"(r[0]), "=r"(r[1]), "=r"(r[2]), "=r"(r[3]) : "r"(a));
}

__device__ __forceinline__ void mma16816h(float* c, const uint32_t* a,
                                          uint32_t b0, uint32_t b1) {
    asm volatile(
        "mma.sync.aligned.m16n8k16.row.col.f32.f16.f16.f32 "
        "{%0,%1,%2,%3}, {%4,%5,%6,%7}, {%8,%9}, {%0,%1,%2,%3};"
        : "+f"(c[0]), "+f"(c[1]), "+f"(c[2]), "+f"(c[3])
        : "r"(a[0]), "r"(a[1]), "r"(a[2]), "r"(a[3]), "r"(b0), "r"(b1));
}

__device__ __forceinline__ void mma16816b(float* c, const uint32_t* a,
                                          uint32_t b0, uint32_t b1) {
    asm volatile(
        "mma.sync.aligned.m16n8k16.row.col.f32.bf16.bf16.f32 "
        "{%0,%1,%2,%3}, {%4,%5,%6,%7}, {%8,%9}, {%0,%1,%2,%3};"
        : "+f"(c[0]), "+f"(c[1]), "+f"(c[2]), "+f"(c[3])
        : "r"(a[0]), "r"(a[1]), "r"(a[2]), "r"(a[3]), "r"(b0), "r"(b1));
}

// pack two fp32 into bf16x2 hi/lo splits
__device__ __forceinline__ void split2b(float x, float y, uint32_t& hi, uint32_t& lo) {
    __nv_bfloat16 hx = __float2bfloat16(x), hy = __float2bfloat16(y);
    float rx = x - __bfloat162float(hx), ry = y - __bfloat162float(hy);
    __nv_bfloat16 lx = __float2bfloat16(rx), ly = __float2bfloat16(ry);
    hi = ((uint32_t)__bfloat16_as_ushort(hy) << 16) | (uint32_t)__bfloat16_as_ushort(hx);
    lo = ((uint32_t)__bfloat16_as_ushort(ly) << 16) | (uint32_t)__bfloat16_as_ushort(lx);
}
// pack two fp32 into one fp16x2 word (single rounding)
__device__ __forceinline__ uint32_t pack2h(float x, float y) {
    __half hx = __float2half(x), hy = __float2half(y);
    return ((uint32_t)__half_as_ushort(hy) << 16) | (uint32_t)__half_as_ushort(hx);
}

// ================= HMMA GEMM: C = oscale*(A fp16, rounded once) @ Wh^T ======
// 256 threads, warp grid 4(M) x 2(N), warp tile 32x64.
// Stage 32KB (A 16K | B 16K), 3-stage ring 96KB -> 2 CTAs/SM.
__device__ __forceinline__ void gemm_mma(const __half* __restrict__ Ah,
                                         const __half* __restrict__ Bh,
                                         float* __restrict__ C, int ldc,
                                         int bm, int bn,
                                         const float* __restrict__ gamma,
                                         const float* __restrict__ beta,
                                         float oscale) {
    constexpr uint32_t STAGE = 32768;
    extern __shared__ char smem[];
    const uint32_t sb = smem_u32(smem);
    const int tid = threadIdx.x, wid = tid >> 5, lane = tid & 31;
    const int m0 = (wid >> 1) * 32;     // warp row base (4 rows of warps)
    const int n0 = (wid & 1) * 64;      // warp col base (2 cols of warps)

    float acc[2][8][4];
#pragma unroll
    for (int i = 0; i < 2; i++)
#pragma unroll
        for (int j = 0; j < 8; j++)
#pragma unroll
            for (int k = 0; k < 4; k++) acc[i][j][k] = 0.f;

    auto load_stage = [&](int st, int k0) {
        uint32_t base = sb + st * STAGE;
#pragma unroll
        for (int tile = 0; tile < 2; tile++) {
            const __half* src = (tile == 0) ? Ah : Bh;
            const int rb = (tile == 0) ? bm : bn;
#pragma unroll
            for (int s = tid; s < 1024; s += 256) {
                int row = s >> 3, ks = s & 7;
                uint32_t dst = base + tile * 16384 +
                               SMEM_SWIZZLE_128B((uint32_t)(row * 128 + ks * 16));
                cp16(dst, src + (size_t)(rb + row) * 1024 + k0 + ks * 8);
            }
        }
        CP_COMMIT();
    };

    const int ar  = lane & 15, ac16 = lane >> 4;             // A 16x16
    const int bsub = lane >> 3, br8 = lane & 7;              // B 16x16
    const int brow = ((bsub & 1) ? 8 : 0) + br8;
    const int bcsel = (bsub >> 1) ? 16 : 0;

    // hoist swizzled intra-stage offsets out of the main loop
    uint32_t aoffs[4][2], boffs[4][4];
#pragma unroll
    for (int t = 0; t < 4; t++) {
#pragma unroll
        for (int mi = 0; mi < 2; mi++)
            aoffs[t][mi] = SMEM_SWIZZLE_128B(
                (uint32_t)((m0 + mi * 16 + ar) * 128 + t * 32 + ac16 * 16));
#pragma unroll
        for (int g = 0; g < 4; g++)
            boffs[t][g] = SMEM_SWIZZLE_128B(
                (uint32_t)((n0 + g * 16 + brow) * 128 + t * 32 + bcsel));
    }

    load_stage(0, 0);       // chunk 0 -> buf 0
    load_stage(1, 64);      // chunk 1 -> buf 1
    for (int i = 0; i < 16; i++) {
        asm volatile("cp.async.wait_group 1;" ::: "memory");   // chunk-i groups done
        __syncthreads();                                       // buf i%3 valid CTA-wide

        if (i < 14) load_stage((i + 2) % 3, (i + 2) * 64);     // prefetch, overlaps MMA
        else CP_COMMIT();                  // empty group keeps wait_group counts aligned

        const uint32_t ahb = sb + (i % 3) * STAGE;
        const uint32_t bhb = ahb + 16384;

#pragma unroll
        for (int t = 0; t < 4; t++) {
            uint32_t ahf[2][4], bhf[4][4];
#pragma unroll
            for (int mi = 0; mi < 2; mi++)
                ldsm4(ahf[mi], ahb + aoffs[t][mi]);
#pragma unroll
            for (int g = 0; g < 4; g++)
                ldsm4(bhf[g], bhb + boffs[t][g]);
#pragma unroll
            for (int mi = 0; mi < 2; mi++)
#pragma unroll
                for (int nj = 0; nj < 8; nj++) {
                    int g = nj >> 1, s2 = nj & 1;
                    mma16816h(acc[mi][nj], ahf[mi], bhf[g][s2], bhf[g][s2 + 2]);
                }
        }
    }

    const int r4 = lane >> 2, c2 = (lane & 3) * 2;

    // -------- fused per-head LayerNorm (head == warp's 64-col span) --------
    if (gamma) {
        float gv[16], bv[16];
#pragma unroll
        for (int nj = 0; nj < 8; nj++)
#pragma unroll
            for (int t = 0; t < 2; t++) {
                int d = nj * 8 + c2 + t;
                gv[nj * 2 + t] = __ldg(gamma + d);
                bv[nj * 2 + t] = __ldg(beta + d);
            }
#pragma unroll
        for (int mi = 0; mi < 2; mi++) {
            float s0 = 0.f, q0 = 0.f, s1 = 0.f, q1 = 0.f;
#pragma unroll
            for (int nj = 0; nj < 8; nj++) {
                float v0 = acc[mi][nj][0], v1 = acc[mi][nj][1];
                float v2 = acc[mi][nj][2], v3 = acc[mi][nj][3];
                s0 += v0 + v1; q0 += v0 * v0 + v1 * v1;
                s1 += v2 + v3; q1 += v2 * v2 + v3 * v3;
            }
#pragma unroll
            for (int o = 1; o <= 2; o <<= 1) {
                s0 += __shfl_xor_sync(0xFFFFFFFFu, s0, o);
                q0 += __shfl_xor_sync(0xFFFFFFFFu, q0, o);
                s1 += __shfl_xor_sync(0xFFFFFFFFu, s1, o);
                q1 += __shfl_xor_sync(0xFFFFFFFFu, q1, o);
            }
            float m0s = s0 * (1.f / 64.f);
            float r0 = rsqrtf(q0 * (1.f / 64.f) - m0s * m0s + 1e-5f);
            float m1s = s1 * (1.f / 64.f);
            float r1 = rsqrtf(q1 * (1.f / 64.f) - m1s * m1s + 1e-5f);
#pragma unroll
            for (int nj = 0; nj < 8; nj++) {
                acc[mi][nj][0] = (acc[mi][nj][0] - m0s) * r0 * gv[nj * 2]     + bv[nj * 2];
                acc[mi][nj][1] = (acc[mi][nj][1] - m0s) * r0 * gv[nj * 2 + 1] + bv[nj * 2 + 1];
                acc[mi][nj][2] = (acc[mi][nj][2] - m1s) * r1 * gv[nj * 2]     + bv[nj * 2];
                acc[mi][nj][3] = (acc[mi][nj][3] - m1s) * r1 * gv[nj * 2 + 1] + bv[nj * 2 + 1];
            }
        }
    }

    // epilogue: c frag * oscale -> gmem fp32
#pragma unroll
    for (int mi = 0; mi < 2; mi++)
#pragma unroll
        for (int nj = 0; nj < 8; nj++) {
            int m = bm + m0 + mi * 16 + r4;
            int n = bn + n0 + nj * 8 + c2;
            float2 v0 = make_float2(acc[mi][nj][0] * oscale, acc[mi][nj][1] * oscale);
            float2 v1 = make_float2(acc[mi][nj][2] * oscale, acc[mi][nj][3] * oscale);
            *reinterpret_cast<float2*>(C + (size_t)m * ldc + n) = v0;
            *reinterpret_cast<float2*>(C + (size_t)(m + 8) * ldc + n) = v1;
        }
}

#define GM_SMEM_1 (3 * 32768)

__global__ __launch_bounds__(256, 2) void proj_tc_kernel(const float* __restrict__ qg,
                                                         const float* __restrict__ qb,
                                                         const float* __restrict__ ag,
                                                         const float* __restrict__ ab,
                                                         const float* __restrict__ bg,
                                                         const float* __restrict__ bbv) {
    const int w = blockIdx.x >> 3, nt = blockIdx.x & 7, bm = blockIdx.y * 128;
    const __half* Bh = g_wh + ((size_t)w << 20);
    float* C;
    const float* gm;
    const float* bt;
    if (w == 0)      { C = g_q; gm = qg; bt = qb; }
    else if (w == 1) { C = g_a; gm = ag; bt = ab; }
    else             { C = g_b; gm = bg; bt = bbv; }
    gemm_mma(g_xh, Bh, C, QAB, bm, nt * 128, gm, bt, 1.0f);
}

__global__ __launch_bounds__(256, 2) void out_tc_kernel(float* __restrict__ out) {
    const int nt = blockIdx.x, bm = blockIdx.y * 128;
    const __half* Bh = g_wh + ((size_t)3 << 20);
    // A-side holds o/64 (rounded once); restore with oscale = 64
    gemm_mma(g_oh, Bh, out, DM, bm, nt * 128, nullptr, nullptr, OSCALE);
}

// ---------------- round fp32 x -> fp16 ----------------
__global__ __launch_bounds__(256) void split_kernel(const float* __restrict__ in) {
    size_t i = ((size_t)blockIdx.x * 256 + threadIdx.x) * 4;
    float4 v = *reinterpret_cast<const float4*>(in + i);
    __half2 h0 = __half2(__float2half(v.x), __float2half(v.y));
    __half2 h1 = __half2(__float2half(v.z), __float2half(v.w));
    *reinterpret_cast<__half2*>(g_xh + i)     = h0;
    *reinterpret_cast<__half2*>(g_xh + i + 2) = h1;
}

// weights: fp32 [K=1024, N=1024] -> transposed fp16 [N, K]; 2 weights/launch
__global__ __launch_bounds__(256) void wsplit2_kernel(const float* __restrict__ WA,
                                                      const float* __restrict__ WB,
                                                      int wbase) {
    const float* W = (blockIdx.z == 0) ? WA : WB;
    const int widx = wbase + blockIdx.z;
    __shared__ float t[32][33];
    const int bx = blockIdx.x * 32;   // n
    const int by = blockIdx.y * 32;   // k
    const int tx = threadIdx.x & 31, ty = threadIdx.x >> 5;
#pragma unroll
    for (int r = 0; r < 32; r += 8)
        t[ty + r][tx] = W[(size_t)(by + ty + r) * 1024 + bx + tx];
    __syncthreads();
    __half* oh = g_wh + ((size_t)widx << 20);
#pragma unroll
    for (int r = 0; r < 32; r += 8) {
        float v = t[tx][ty + r];                          // = W[by+tx][bx+ty+r]
        size_t oi = (size_t)(bx + ty + r) * 1024 + by + tx;
        oh[oi] = __float2half(v);
    }
}

// ---------------- exclusive cumsum of a along time (two-pass) ----------------
__global__ __launch_bounds__(256) void chunksum_kernel() {
    int gid = blockIdx.x * 256 + threadIdx.x;
    int col = gid % QAB;
    int c   = (gid / QAB) % NC;
    int b   = gid / (QAB * NC);
    const float* p = g_a + (size_t)(b * Tt + c * CH) * QAB + col;
    float s = 0.f;
#pragma unroll 8
    for (int r = 0; r < CH; r++) s += p[(size_t)r * QAB];
    g_cs[(b * NC + c) * QAB + col] = s;
}

__global__ __launch_bounds__(256) void excl_kernel() {
    int gid = blockIdx.x * 256 + threadIdx.x;
    int col = gid % QAB;
    int c   = (gid / QAB) % NC;
    int b   = gid / (QAB * NC);
    float off = 0.f;
    for (int cc = 0; cc < c; cc++) off += g_cs[(b * NC + cc) * QAB + col];
    const float* pa = g_a   + (size_t)(b * Tt + c * CH) * QAB + col;
    float*       pe = g_aex + (size_t)(b * Tt + c * CH) * QAB + col;
    float run = off;
#pragma unroll 8
    for (int r = 0; r < CH; r++) {
        pe[(size_t)r * QAB] = run;
        run += pa[(size_t)r * QAB];
    }
}

// -------- per-chunk outer product, stored transposed: P^T[e][d] = sum_t B[t][e] Aex[t][d]
__global__ __launch_bounds__(256) void chunkP_kernel() {
    int c = blockIdx.x & (NC - 1);
    int h = (blockIdx.x >> 5) & (Hh - 1);
    int b = blockIdx.x >> 9;
    __shared__ float Ax[64][64];
    __shared__ float Bx[64][64];
    int tid = threadIdx.x;
    size_t base = (size_t)(b * Tt + c * CH) * QAB + h * Dd;
    for (int idx = tid; idx < 4096; idx += 256) {
        int t = idx >> 6, d = idx & 63;
        Ax[t][d] = g_aex[base + (size_t)t * QAB + d];
        Bx[t][d] = g_b [base + (size_t)t * QAB + d];
    }
    __syncthreads();
    int dr = (tid >> 4) * 4, ec = (tid & 15) * 4;
    float acc[4][4] = {};
#pragma unroll 4
    for (int t = 0; t < 64; t++) {
        float av[4], bv[4];
#pragma unroll
        for (int i = 0; i < 4; i++) av[i] = Ax[t][dr + i];
#pragma unroll
        for (int j = 0; j < 4; j++) bv[j] = Bx[t][ec + j];
#pragma unroll
        for (int i = 0; i < 4; i++)
#pragma unroll
            for (int j = 0; j < 4; j++)
                acc[i][j] = fmaf(av[i], bv[j], acc[i][j]);
    }
    size_t pb = ((size_t)((b * Hh + h) * NC + c)) * 4096;
#pragma unroll
    for (int j = 0; j < 4; j++) {       // transposed store: row e, col d
        float4 v = make_float4(acc[0][j], acc[1][j], acc[2][j], acc[3][j]);
        *reinterpret_cast<float4*>(g_P + pb + (size_t)(ec + j) * 64 + dr) = v;
    }
}

// ---------------- elementwise exclusive scan of P^T over chunks -> M^T -------
__global__ __launch_bounds__(256) void scanM_kernel() {
    int gid = blockIdx.x * 256 + threadIdx.x;
    int de = gid & 4095;
    int bh = gid >> 12;
    size_t base = (size_t)bh * NC * 4096 + de;
    float run = 0.f;
#pragma unroll
    for (int c = 0; c < NC; c++) {
        g_M[base + (size_t)c * 4096] = run;
        run += g_P[base + (size_t)c * 4096];
    }
}

// ---------------- chunk attention via HMMA (bf16 3-term internals) -----------
// S = tril(Q Aex^T);  O = Q M^T_rows + S B^T_rows;  output -> (o/64) fp16
#define OQ_H 0
#define OQ_L 8192
#define OA_H 16384
#define OA_L 24576
#define OB_H 32768
#define OB_L 40960
#define OM_H 49152
#define OM_L 57344
#define ATT_SMEM 65536

__global__ __launch_bounds__(128, 1) void attn_kernel() {
    extern __shared__ char smem[];
    const uint32_t sb = smem_u32(smem);
    int c = blockIdx.x & (NC - 1);
    int h = (blockIdx.x >> 5) & (Hh - 1);
    int b = blockIdx.x >> 9;
    int tid = threadIdx.x, wid = tid >> 5, lane = tid & 31;
    size_t base  = (size_t)(b * Tt + c * CH) * QAB + h * Dd;
    size_t mbase = ((size_t)((b * Hh + h) * NC + c)) * 4096;

    // load + convert to split bf16 smem (SW128 rows of 128B)
    for (int idx = tid; idx < 4096; idx += 128) {
        int t = idx >> 6, d = idx & 63;
        size_t go = base + (size_t)t * QAB + d;
        float q  = g_q[go];
        float a  = g_aex[go];
        float bv = g_b[go];
        float m  = g_M[mbase + idx];                       // row e=t, col d (M^T)
        uint32_t offr = SMEM_SWIZZLE_128B((uint32_t)(t * 128 + d * 2));
        uint32_t offt = SMEM_SWIZZLE_128B((uint32_t)(d * 128 + t * 2));  // B transposed
        __nv_bfloat16 hh, ll;
        hh = __float2bfloat16(q);  ll = __float2bfloat16(q - __bfloat162float(hh));
        *(__nv_bfloat16*)(smem + OQ_H + offr) = hh;
        *(__nv_bfloat16*)(smem + OQ_L + offr) = ll;
        hh = __float2bfloat16(a);  ll = __float2bfloat16(a - __bfloat162float(hh));
        *(__nv_bfloat16*)(smem + OA_H + offr) = hh;
        *(__nv_bfloat16*)(smem + OA_L + offr) = ll;
        hh = __float2bfloat16(bv); ll = __float2bfloat16(bv - __bfloat162float(hh));
        *(__nv_bfloat16*)(smem + OB_H + offt) = hh;
        *(__nv_bfloat16*)(smem + OB_L + offt) = ll;
        hh = __float2bfloat16(m);  ll = __float2bfloat16(m - __bfloat162float(hh));
        *(__nv_bfloat16*)(smem + OM_H + offr) = hh;
        *(__nv_bfloat16*)(smem + OM_L + offr) = ll;
    }
    __syncthreads();

    const int m0 = wid * 16;
    const int ar = lane & 15, ac16 = lane >> 4;
    const int bsub = lane >> 3, br8 = lane & 7;
    const int brow = ((bsub & 1) ? 8 : 0) + br8;
    const int bcsel = (bsub >> 1) ? 16 : 0;
    const int r4 = lane >> 2, c2 = (lane & 3) * 2;

    // ---- gemm1: S = Q @ Aex^T ----
    float sacc[8][4];
#pragma unroll
    for (int j = 0; j < 8; j++)
#pragma unroll
        for (int k = 0; k < 4; k++) sacc[j][k] = 0.f;
#pragma unroll
    for (int t = 0; t < 4; t++) {
        uint32_t qh[4], ql[4], bh_[4][4], bl_[4][4];
        uint32_t aoff = SMEM_SWIZZLE_128B((uint32_t)((m0 + ar) * 128 + t * 32 + ac16 * 16));
        ldsm4(qh, sb + OQ_H + aoff);
        ldsm4(ql, sb + OQ_L + aoff);
#pragma unroll
        for (int g = 0; g < 4; g++) {
            uint32_t boff = SMEM_SWIZZLE_128B((uint32_t)((g * 16 + brow) * 128 + t * 32 + bcsel));
            ldsm4(bh_[g], sb + OA_H + boff);
            ldsm4(bl_[g], sb + OA_L + boff);
        }
#pragma unroll
        for (int nj = 0; nj < 8; nj++) {
            int g = nj >> 1, s2 = nj & 1;
            mma16816b(sacc[nj], qh, bh_[g][s2], bh_[g][s2 + 2]);
            mma16816b(sacc[nj], qh, bl_[g][s2], bl_[g][s2 + 2]);
            mma16816b(sacc[nj], ql, bh_[g][s2], bh_[g][s2 + 2]);
        }
    }

    // causal mask (keep s <= t)
    const int row0 = m0 + r4, row1 = row0 + 8;
#pragma unroll
    for (int nj = 0; nj < 8; nj++) {
        int col = nj * 8 + c2;
        if (col     > row0) sacc[nj][0] = 0.f;
        if (col + 1 > row0) sacc[nj][1] = 0.f;
        if (col     > row1) sacc[nj][2] = 0.f;
        if (col + 1 > row1) sacc[nj][3] = 0.f;
    }

    // S C-frags -> A-frags (hi/lo bf16), pure register repack
    uint32_t sh[4][4], sl[4][4];
#pragma unroll
    for (int j = 0; j < 4; j++) {
        split2b(sacc[2 * j][0],     sacc[2 * j][1],     sh[j][0], sl[j][0]);
        split2b(sacc[2 * j][2],     sacc[2 * j][3],     sh[j][1], sl[j][1]);
        split2b(sacc[2 * j + 1][0], sacc[2 * j + 1][1], sh[j][2], sl[j][2]);
        split2b(sacc[2 * j + 1][2], sacc[2 * j + 1][3], sh[j][3], sl[j][3]);
    }

    // ---- gemm2: O = Q @ M^T  (+ gemm3: O += S @ B^T) ----
    float oacc[8][4];
#pragma unroll
    for (int j = 0; j < 8; j++)
#pragma unroll
        for (int k = 0; k < 4; k++) oacc[j][k] = 0.f;
#pragma unroll
    for (int t = 0; t < 4; t++) {
        uint32_t qh[4], ql[4], bh_[4][4], bl_[4][4];
        uint32_t aoff = SMEM_SWIZZLE_128B((uint32_t)((m0 + ar) * 128 + t * 32 + ac16 * 16));
        ldsm4(qh, sb + OQ_H + aoff);
        ldsm4(ql, sb + OQ_L + aoff);
#pragma unroll
        for (int g = 0; g < 4; g++) {
            uint32_t boff = SMEM_SWIZZLE_128B((uint32_t)((g * 16 + brow) * 128 + t * 32 + bcsel));
            ldsm4(bh_[g], sb + OM_H + boff);
            ldsm4(bl_[g], sb + OM_L + boff);
        }
#pragma unroll
        for (int nj = 0; nj < 8; nj++) {
            int g = nj >> 1, s2 = nj & 1;
            mma16816b(oacc[nj], qh, bh_[g][s2], bh_[g][s2 + 2]);
            mma16816b(oacc[nj], qh, bl_[g][s2], bl_[g][s2 + 2]);
            mma16816b(oacc[nj], ql, bh_[g][s2], bh_[g][s2 + 2]);
        }
    }
#pragma unroll
    for (int j = 0; j < 4; j++) {              // k-tile over s = 16j..16j+15
        uint32_t bh_[4][4], bl_[4][4];
#pragma unroll
        for (int g = 0; g < 4; g++) {
            uint32_t boff = SMEM_SWIZZLE_128B((uint32_t)((g * 16 + brow) * 128 + j * 32 + bcsel));
            ldsm4(bh_[g], sb + OB_H + boff);
            ldsm4(bl_[g], sb + OB_L + boff);
        }
#pragma unroll
        for (int nj = 0; nj < 8; nj++) {
            int g = nj >> 1, s2 = nj & 1;
            mma16816b(oacc[nj], sh[j], bh_[g][s2], bh_[g][s2 + 2]);
            mma16816b(oacc[nj], sh[j], bl_[g][s2], bl_[g][s2 + 2]);
            mma16816b(oacc[nj], sl[j], bh_[g][s2], bh_[g][s2 + 2]);
        }
    }

    // epilogue: (o/64) fp32 -> fp16 (rounded once) gmem
#pragma unroll
    for (int nj = 0; nj < 8; nj++) {
        int col = nj * 8 + c2;
        size_t r0o = base + (size_t)row0 * QAB + col;
        size_t r1o = base + (size_t)row1 * QAB + col;
        *reinterpret_cast<uint32_t*>(g_oh + r0o) =
            pack2h(oacc[nj][0] * ISCALE, oacc[nj][1] * ISCALE);
        *reinterpret_cast<uint32_t*>(g_oh + r1o) =
            pack2h(oacc[nj][2] * ISCALE, oacc[nj][3] * ISCALE);
    }
}

// ---------------- launcher ----------------
extern "C" void kernel_launch(void* const* d_in, const int* in_sizes, int n_in,
                              void* d_out, int out_size) {
    const float* x  = (const float*)d_in[0];
    const float* Wq = (const float*)d_in[1];
    const float* Wa = (const float*)d_in[2];
    const float* Wb = (const float*)d_in[3];
    const float* Wo = (const float*)d_in[4];
    const float* qg = (const float*)d_in[5];
    const float* qb = (const float*)d_in[6];
    const float* ag = (const float*)d_in[7];
    const float* ab = (const float*)d_in[8];
    const float* bg = (const float*)d_in[9];
    const float* bbv = (const float*)d_in[10];
    float* out = (float*)d_out;

    cudaFuncSetAttribute(proj_tc_kernel, cudaFuncAttributeMaxDynamicSharedMemorySize, GM_SMEM_1);
    cudaFuncSetAttribute(out_tc_kernel,  cudaFuncAttributeMaxDynamicSharedMemorySize, GM_SMEM_1);
    cudaFuncSetAttribute(attn_kernel,    cudaFuncAttributeMaxDynamicSharedMemorySize, ATT_SMEM);

    split_kernel<<<4096, 256>>>(x);                              // launch 0
    wsplit2_kernel<<<dim3(32, 32, 2), 256>>>(Wq, Wa, 0);         // launch 1
    wsplit2_kernel<<<dim3(32, 32, 2), 256>>>(Wb, Wo, 2);         // launch 2

    proj_tc_kernel<<<dim3(24, 32), 256, GM_SMEM_1>>>(qg, qb, ag, ab, bg, bbv);  // launch 3 (profiled)

    chunksum_kernel<<<(Bb * QAB * NC) / 256, 256>>>();
    excl_kernel<<<(Bb * QAB * NC) / 256, 256>>>();

    chunkP_kernel<<<Bb * Hh * NC, 256>>>();
    scanM_kernel<<<(Bb * Hh * 4096) / 256, 256>>>();
    attn_kernel<<<Bb * Hh * NC, 128, ATT_SMEM>>>();

    out_tc_kernel<<<dim3(8, 32), 256, GM_SMEM_1>>>(out);
}

// round 17
// speedup vs baseline: 2.0702x; 1.0634x over previous
#include <cuda_runtime.h>
#include <cuda_fp16.h>
#include <cuda_bf16.h>
#include <cstdint>

#define Bb   2
#define Tt   2048
#define DM   1024
#define Hh   16
#define Dd   64
#define BT   4096          // B*T
#define QAB  1024          // H*D
#define CH   64            // chunk length
#define NC   32            // T / CH

#define OSCALE 64.0f
#define ISCALE (1.0f / 64.0f)

// ---------------- scratch (device globals; no allocs allowed) ----------------
__device__ float g_q  [BT * QAB];
__device__ float g_a  [BT * QAB];
__device__ float g_b  [BT * QAB];
__device__ float g_aex[BT * QAB];
__device__ float g_P  [Bb * Hh * NC * Dd * Dd];   // stored TRANSPOSED: [e][d]
__device__ float g_M  [Bb * Hh * NC * Dd * Dd];   // exclusive scan of P^T = M^T
__device__ float g_cs [Bb * QAB * NC];

// fp16 operands (single-rounded A-sides)
__device__ __half g_xh[BT * DM];      // x rounded (1-term proj)
__device__ __half g_oh[BT * QAB];     // o/64 rounded (1-term out GEMM)
__device__ __half g_wh[4u << 20];     // 4 weights, each [N=1024][K=1024] (transposed)

// ================= helpers ==================
__device__ __forceinline__ uint32_t smem_u32(const void* p) {
    uint32_t a;
    asm("{ .reg .u64 t; cvta.to.shared.u64 t, %1; cvt.u32.u64 %0, t; }" : "=r"(a) : "l"(p));
    return a;
}
#define SMEM_SWIZZLE_128B(off) ((off) ^ (((off) >> 3) & 0x70))

__device__ __forceinline__ void cp16(uint32_t dst, const void* src) {
    asm volatile("cp.async.cg.shared.global [%0], [%1], 16;" :: "r"(dst), "l"(src));
}
#define CP_COMMIT() asm volatile("cp.async.commit_group;" ::: "memory")

__device__ __forceinline__ void ldsm4(uint32_t* r, uint32_t a) {
    asm volatile("ldmatrix.sync.aligned.m8n8.x4.shared.b16 {%0,%1,%2,%3}, [%4];"
                 : "=r"(r[0]), "=r"(r[1]), "=r"(r[2]), "=r"(r[3]) : "r"(a));
}

__device__ __forceinline__ void mma16816h(float* c, const uint32_t* a,
                                          uint32_t b0, uint32_t b1) {
    asm volatile(
        "mma.sync.aligned.m16n8k16.row.col.f32.f16.f16.f32 "
        "{%0,%1,%2,%3}, {%4,%5,%6,%7}, {%8,%9}, {%0,%1,%2,%3};"
        : "+f"(c[0]), "+f"(c[1]), "+f"(c[2]), "+f"(c[3])
        : "r"(a[0]), "r"(a[1]), "r"(a[2]), "r"(a[3]), "r"(b0), "r"(b1));
}

__device__ __forceinline__ void mma16816b(float* c, const uint32_t* a,
                                          uint32_t b0, uint32_t b1) {
    asm volatile(
        "mma.sync.aligned.m16n8k16.row.col.f32.bf16.bf16.f32 "
        "{%0,%1,%2,%3}, {%4,%5,%6,%7}, {%8,%9}, {%0,%1,%2,%3};"
        : "+f"(c[0]), "+f"(c[1]), "+f"(c[2]), "+f"(c[3])
        : "r"(a[0]), "r"(a[1]), "r"(a[2]), "r"(a[3]), "r"(b0), "r"(b1));
}

// pack two fp32 into bf16x2 hi/lo splits
__device__ __forceinline__ void split2b(float x, float y, uint32_t& hi, uint32_t& lo) {
    __nv_bfloat16 hx = __float2bfloat16(x), hy = __float2bfloat16(y);
    float rx = x - __bfloat162float(hx), ry = y - __bfloat162float(hy);
    __nv_bfloat16 lx = __float2bfloat16(rx), ly = __float2bfloat16(ry);
    hi = ((uint32_t)__bfloat16_as_ushort(hy) << 16) | (uint32_t)__bfloat16_as_ushort(hx);
    lo = ((uint32_t)__bfloat16_as_ushort(ly) << 16) | (uint32_t)__bfloat16_as_ushort(lx);
}
// pack two fp32 into one fp16x2 word (single rounding)
__device__ __forceinline__ uint32_t pack2h(float x, float y) {
    __half hx = __float2half(x), hy = __float2half(y);
    return ((uint32_t)__half_as_ushort(hy) << 16) | (uint32_t)__half_as_ushort(hx);
}

// ================= HMMA GEMM: C = oscale*(A fp16, rounded once) @ Wh^T ======
// 256 threads, warp grid 4(M) x 2(N), warp tile 32x64.
// Stage 32KB (A 16K | B 16K), 3-stage ring 96KB -> 2 CTAs/SM.
__device__ __forceinline__ void gemm_mma(const __half* __restrict__ Ah,
                                         const __half* __restrict__ Bh,
                                         float* __restrict__ C, int ldc,
                                         int bm, int bn,
                                         const float* __restrict__ gamma,
                                         const float* __restrict__ beta,
                                         float oscale) {
    constexpr uint32_t STAGE = 32768;
    extern __shared__ char smem[];
    const uint32_t sb = smem_u32(smem);
    const int tid = threadIdx.x, wid = tid >> 5, lane = tid & 31;
    const int m0 = (wid >> 1) * 32;     // warp row base (4 rows of warps)
    const int n0 = (wid & 1) * 64;      // warp col base (2 cols of warps)

    float acc[2][8][4];
#pragma unroll
    for (int i = 0; i < 2; i++)
#pragma unroll
        for (int j = 0; j < 8; j++)
#pragma unroll
            for (int k = 0; k < 4; k++) acc[i][j][k] = 0.f;

    auto load_stage = [&](int st, int k0) {
        uint32_t base = sb + st * STAGE;
#pragma unroll
        for (int tile = 0; tile < 2; tile++) {
            const __half* src = (tile == 0) ? Ah : Bh;
            const int rb = (tile == 0) ? bm : bn;
#pragma unroll
            for (int s = tid; s < 1024; s += 256) {
                int row = s >> 3, ks = s & 7;
                uint32_t dst = base + tile * 16384 +
                               SMEM_SWIZZLE_128B((uint32_t)(row * 128 + ks * 16));
                cp16(dst, src + (size_t)(rb + row) * 1024 + k0 + ks * 8);
            }
        }
        CP_COMMIT();
    };

    const int ar  = lane & 15, ac16 = lane >> 4;             // A 16x16
    const int bsub = lane >> 3, br8 = lane & 7;              // B 16x16
    const int brow = ((bsub & 1) ? 8 : 0) + br8;
    const int bcsel = (bsub >> 1) ? 16 : 0;

    // hoist swizzled intra-stage offsets out of the main loop
    uint32_t aoffs[4][2], boffs[4][4];
#pragma unroll
    for (int t = 0; t < 4; t++) {
#pragma unroll
        for (int mi = 0; mi < 2; mi++)
            aoffs[t][mi] = SMEM_SWIZZLE_128B(
                (uint32_t)((m0 + mi * 16 + ar) * 128 + t * 32 + ac16 * 16));
#pragma unroll
        for (int g = 0; g < 4; g++)
            boffs[t][g] = SMEM_SWIZZLE_128B(
                (uint32_t)((n0 + g * 16 + brow) * 128 + t * 32 + bcsel));
    }

    load_stage(0, 0);       // chunk 0 -> buf 0
    load_stage(1, 64);      // chunk 1 -> buf 1
    for (int i = 0; i < 16; i++) {
        asm volatile("cp.async.wait_group 1;" ::: "memory");   // chunk-i groups done
        __syncthreads();                                       // buf i%3 valid CTA-wide

        if (i < 14) load_stage((i + 2) % 3, (i + 2) * 64);     // prefetch, overlaps MMA
        else CP_COMMIT();                  // empty group keeps wait_group counts aligned

        const uint32_t ahb = sb + (i % 3) * STAGE;
        const uint32_t bhb = ahb + 16384;

#pragma unroll
        for (int t = 0; t < 4; t++) {
            uint32_t ahf[2][4], bhf[4][4];
#pragma unroll
            for (int mi = 0; mi < 2; mi++)
                ldsm4(ahf[mi], ahb + aoffs[t][mi]);
#pragma unroll
            for (int g = 0; g < 4; g++)
                ldsm4(bhf[g], bhb + boffs[t][g]);
#pragma unroll
            for (int mi = 0; mi < 2; mi++)
#pragma unroll
                for (int nj = 0; nj < 8; nj++) {
                    int g = nj >> 1, s2 = nj & 1;
                    mma16816h(acc[mi][nj], ahf[mi], bhf[g][s2], bhf[g][s2 + 2]);
                }
        }
    }

    const int r4 = lane >> 2, c2 = (lane & 3) * 2;

    // -------- fused per-head LayerNorm (head == warp's 64-col span) --------
    if (gamma) {
        float gv[16], bv[16];
#pragma unroll
        for (int nj = 0; nj < 8; nj++)
#pragma unroll
            for (int t = 0; t < 2; t++) {
                int d = nj * 8 + c2 + t;
                gv[nj * 2 + t] = __ldg(gamma + d);
                bv[nj * 2 + t] = __ldg(beta + d);
            }
#pragma unroll
        for (int mi = 0; mi < 2; mi++) {
            float s0 = 0.f, q0 = 0.f, s1 = 0.f, q1 = 0.f;
#pragma unroll
            for (int nj = 0; nj < 8; nj++) {
                float v0 = acc[mi][nj][0], v1 = acc[mi][nj][1];
                float v2 = acc[mi][nj][2], v3 = acc[mi][nj][3];
                s0 += v0 + v1; q0 += v0 * v0 + v1 * v1;
                s1 += v2 + v3; q1 += v2 * v2 + v3 * v3;
            }
#pragma unroll
            for (int o = 1; o <= 2; o <<= 1) {
                s0 += __shfl_xor_sync(0xFFFFFFFFu, s0, o);
                q0 += __shfl_xor_sync(0xFFFFFFFFu, q0, o);
                s1 += __shfl_xor_sync(0xFFFFFFFFu, s1, o);
                q1 += __shfl_xor_sync(0xFFFFFFFFu, q1, o);
            }
            float m0s = s0 * (1.f / 64.f);
            float r0 = rsqrtf(q0 * (1.f / 64.f) - m0s * m0s + 1e-5f);
            float m1s = s1 * (1.f / 64.f);
            float r1 = rsqrtf(q1 * (1.f / 64.f) - m1s * m1s + 1e-5f);
#pragma unroll
            for (int nj = 0; nj < 8; nj++) {
                acc[mi][nj][0] = (acc[mi][nj][0] - m0s) * r0 * gv[nj * 2]     + bv[nj * 2];
                acc[mi][nj][1] = (acc[mi][nj][1] - m0s) * r0 * gv[nj * 2 + 1] + bv[nj * 2 + 1];
                acc[mi][nj][2] = (acc[mi][nj][2] - m1s) * r1 * gv[nj * 2]     + bv[nj * 2];
                acc[mi][nj][3] = (acc[mi][nj][3] - m1s) * r1 * gv[nj * 2 + 1] + bv[nj * 2 + 1];
            }
        }
    }

    // epilogue: c frag * oscale -> gmem fp32
#pragma unroll
    for (int mi = 0; mi < 2; mi++)
#pragma unroll
        for (int nj = 0; nj < 8; nj++) {
            int m = bm + m0 + mi * 16 + r4;
            int n = bn + n0 + nj * 8 + c2;
            float2 v0 = make_float2(acc[mi][nj][0] * oscale, acc[mi][nj][1] * oscale);
            float2 v1 = make_float2(acc[mi][nj][2] * oscale, acc[mi][nj][3] * oscale);
            *reinterpret_cast<float2*>(C + (size_t)m * ldc + n) = v0;
            *reinterpret_cast<float2*>(C + (size_t)(m + 8) * ldc + n) = v1;
        }
}

#define GM_SMEM_1 (3 * 32768)

// one projection GEMM (per-weight launch for stream-level overlap)
__global__ __launch_bounds__(256, 2) void proj_w_kernel(int w,
                                                        const float* __restrict__ gm,
                                                        const float* __restrict__ bt) {
    const int nt = blockIdx.x, bm = blockIdx.y * 128;
    const __half* Bh = g_wh + ((size_t)w << 20);
    float* C = (w == 0) ? g_q : ((w == 1) ? g_a : g_b);
    gemm_mma(g_xh, Bh, C, QAB, bm, nt * 128, gm, bt, 1.0f);
}

__global__ __launch_bounds__(256, 2) void out_tc_kernel(float* __restrict__ out) {
    const int nt = blockIdx.x, bm = blockIdx.y * 128;
    const __half* Bh = g_wh + ((size_t)3 << 20);
    // A-side holds o/64 (rounded once); restore with oscale = 64
    gemm_mma(g_oh, Bh, out, DM, bm, nt * 128, nullptr, nullptr, OSCALE);
}

// ---------------- round fp32 x -> fp16 ----------------
__global__ __launch_bounds__(256) void split_kernel(const float* __restrict__ in) {
    size_t i = ((size_t)blockIdx.x * 256 + threadIdx.x) * 4;
    float4 v = *reinterpret_cast<const float4*>(in + i);
    __half2 h0 = __half2(__float2half(v.x), __float2half(v.y));
    __half2 h1 = __half2(__float2half(v.z), __float2half(v.w));
    *reinterpret_cast<__half2*>(g_xh + i)     = h0;
    *reinterpret_cast<__half2*>(g_xh + i + 2) = h1;
}

// weights: fp32 [K=1024, N=1024] -> transposed fp16 [N, K]; 2 weights/launch
__global__ __launch_bounds__(256) void wsplit2_kernel(const float* __restrict__ WA,
                                                      const float* __restrict__ WB,
                                                      int wbase) {
    const float* W = (blockIdx.z == 0) ? WA : WB;
    const int widx = wbase + blockIdx.z;
    __shared__ float t[32][33];
    const int bx = blockIdx.x * 32;   // n
    const int by = blockIdx.y * 32;   // k
    const int tx = threadIdx.x & 31, ty = threadIdx.x >> 5;
#pragma unroll
    for (int r = 0; r < 32; r += 8)
        t[ty + r][tx] = W[(size_t)(by + ty + r) * 1024 + bx + tx];
    __syncthreads();
    __half* oh = g_wh + ((size_t)widx << 20);
#pragma unroll
    for (int r = 0; r < 32; r += 8) {
        float v = t[tx][ty + r];                          // = W[by+tx][bx+ty+r]
        size_t oi = (size_t)(bx + ty + r) * 1024 + by + tx;
        oh[oi] = __float2half(v);
    }
}

// ---------------- exclusive cumsum of a along time (two-pass) ----------------
__global__ __launch_bounds__(256) void chunksum_kernel() {
    int gid = blockIdx.x * 256 + threadIdx.x;
    int col = gid % QAB;
    int c   = (gid / QAB) % NC;
    int b   = gid / (QAB * NC);
    const float* p = g_a + (size_t)(b * Tt + c * CH) * QAB + col;
    float s = 0.f;
#pragma unroll 8
    for (int r = 0; r < CH; r++) s += p[(size_t)r * QAB];
    g_cs[(b * NC + c) * QAB + col] = s;
}

__global__ __launch_bounds__(256) void excl_kernel() {
    int gid = blockIdx.x * 256 + threadIdx.x;
    int col = gid % QAB;
    int c   = (gid / QAB) % NC;
    int b   = gid / (QAB * NC);
    float off = 0.f;
    for (int cc = 0; cc < c; cc++) off += g_cs[(b * NC + cc) * QAB + col];
    const float* pa = g_a   + (size_t)(b * Tt + c * CH) * QAB + col;
    float*       pe = g_aex + (size_t)(b * Tt + c * CH) * QAB + col;
    float run = off;
#pragma unroll 8
    for (int r = 0; r < CH; r++) {
        pe[(size_t)r * QAB] = run;
        run += pa[(size_t)r * QAB];
    }
}

// -------- per-chunk outer product, stored transposed: P^T[e][d] = sum_t B[t][e] Aex[t][d]
__global__ __launch_bounds__(256) void chunkP_kernel() {
    int c = blockIdx.x & (NC - 1);
    int h = (blockIdx.x >> 5) & (Hh - 1);
    int b = blockIdx.x >> 9;
    __shared__ float Ax[64][64];
    __shared__ float Bx[64][64];
    int tid = threadIdx.x;
    size_t base = (size_t)(b * Tt + c * CH) * QAB + h * Dd;
    for (int idx = tid; idx < 4096; idx += 256) {
        int t = idx >> 6, d = idx & 63;
        Ax[t][d] = g_aex[base + (size_t)t * QAB + d];
        Bx[t][d] = g_b [base + (size_t)t * QAB + d];
    }
    __syncthreads();
    int dr = (tid >> 4) * 4, ec = (tid & 15) * 4;
    float acc[4][4] = {};
#pragma unroll 4
    for (int t = 0; t < 64; t++) {
        float av[4], bv[4];
#pragma unroll
        for (int i = 0; i < 4; i++) av[i] = Ax[t][dr + i];
#pragma unroll
        for (int j = 0; j < 4; j++) bv[j] = Bx[t][ec + j];
#pragma unroll
        for (int i = 0; i < 4; i++)
#pragma unroll
            for (int j = 0; j < 4; j++)
                acc[i][j] = fmaf(av[i], bv[j], acc[i][j]);
    }
    size_t pb = ((size_t)((b * Hh + h) * NC + c)) * 4096;
#pragma unroll
    for (int j = 0; j < 4; j++) {       // transposed store: row e, col d
        float4 v = make_float4(acc[0][j], acc[1][j], acc[2][j], acc[3][j]);
        *reinterpret_cast<float4*>(g_P + pb + (size_t)(ec + j) * 64 + dr) = v;
    }
}

// ---------------- elementwise exclusive scan of P^T over chunks -> M^T -------
__global__ __launch_bounds__(256) void scanM_kernel() {
    int gid = blockIdx.x * 256 + threadIdx.x;
    int de = gid & 4095;
    int bh = gid >> 12;
    size_t base = (size_t)bh * NC * 4096 + de;
    float run = 0.f;
#pragma unroll
    for (int c = 0; c < NC; c++) {
        g_M[base + (size_t)c * 4096] = run;
        run += g_P[base + (size_t)c * 4096];
    }
}

// ---------------- chunk attention via HMMA (bf16 3-term internals) -----------
// S = tril(Q Aex^T);  O = Q M^T_rows + S B^T_rows;  output -> (o/64) fp16
// Causal skip: S-tiles entirely above the diagonal (cols > warp max row) are
// fully masked -> skip their ldsm+MMA in gemm1, repack, and gemm3 k-tiles.
#define OQ_H 0
#define OQ_L 8192
#define OA_H 16384
#define OA_L 24576
#define OB_H 32768
#define OB_L 40960
#define OM_H 49152
#define OM_L 57344
#define ATT_SMEM 65536

__global__ __launch_bounds__(128, 1) void attn_kernel() {
    extern __shared__ char smem[];
    const uint32_t sb = smem_u32(smem);
    int c = blockIdx.x & (NC - 1);
    int h = (blockIdx.x >> 5) & (Hh - 1);
    int b = blockIdx.x >> 9;
    int tid = threadIdx.x, wid = tid >> 5, lane = tid & 31;
    size_t base  = (size_t)(b * Tt + c * CH) * QAB + h * Dd;
    size_t mbase = ((size_t)((b * Hh + h) * NC + c)) * 4096;

    // load + convert to split bf16 smem (SW128 rows of 128B)
    for (int idx = tid; idx < 4096; idx += 128) {
        int t = idx >> 6, d = idx & 63;
        size_t go = base + (size_t)t * QAB + d;
        float q  = g_q[go];
        float a  = g_aex[go];
        float bv = g_b[go];
        float m  = g_M[mbase + idx];                       // row e=t, col d (M^T)
        uint32_t offr = SMEM_SWIZZLE_128B((uint32_t)(t * 128 + d * 2));
        uint32_t offt = SMEM_SWIZZLE_128B((uint32_t)(d * 128 + t * 2));  // B transposed
        __nv_bfloat16 hh, ll;
        hh = __float2bfloat16(q);  ll = __float2bfloat16(q - __bfloat162float(hh));
        *(__nv_bfloat16*)(smem + OQ_H + offr) = hh;
        *(__nv_bfloat16*)(smem + OQ_L + offr) = ll;
        hh = __float2bfloat16(a);  ll = __float2bfloat16(a - __bfloat162float(hh));
        *(__nv_bfloat16*)(smem + OA_H + offr) = hh;
        *(__nv_bfloat16*)(smem + OA_L + offr) = ll;
        hh = __float2bfloat16(bv); ll = __float2bfloat16(bv - __bfloat162float(hh));
        *(__nv_bfloat16*)(smem + OB_H + offt) = hh;
        *(__nv_bfloat16*)(smem + OB_L + offt) = ll;
        hh = __float2bfloat16(m);  ll = __float2bfloat16(m - __bfloat162float(hh));
        *(__nv_bfloat16*)(smem + OM_H + offr) = hh;
        *(__nv_bfloat16*)(smem + OM_L + offr) = ll;
    }
    __syncthreads();

    const int m0 = wid * 16;
    const int ar = lane & 15, ac16 = lane >> 4;
    const int bsub = lane >> 3, br8 = lane & 7;
    const int brow = ((bsub & 1) ? 8 : 0) + br8;
    const int bcsel = (bsub >> 1) ? 16 : 0;
    const int r4 = lane >> 2, c2 = (lane & 3) * 2;

    // ---- gemm1: S = Q @ Aex^T  (skip tiles fully above diagonal: g > wid) ----
    float sacc[8][4];
#pragma unroll
    for (int j = 0; j < 8; j++)
#pragma unroll
        for (int k = 0; k < 4; k++) sacc[j][k] = 0.f;
#pragma unroll
    for (int t = 0; t < 4; t++) {
        uint32_t qh[4], ql[4], bh_[4][4], bl_[4][4];
        uint32_t aoff = SMEM_SWIZZLE_128B((uint32_t)((m0 + ar) * 128 + t * 32 + ac16 * 16));
        ldsm4(qh, sb + OQ_H + aoff);
        ldsm4(ql, sb + OQ_L + aoff);
#pragma unroll
        for (int g = 0; g < 4; g++) {
            if (g > wid) continue;                         // cols 16g.. > m0+15: masked
            uint32_t boff = SMEM_SWIZZLE_128B((uint32_t)((g * 16 + brow) * 128 + t * 32 + bcsel));
            ldsm4(bh_[g], sb + OA_H + boff);
            ldsm4(bl_[g], sb + OA_L + boff);
        }
#pragma unroll
        for (int nj = 0; nj < 8; nj++) {
            int g = nj >> 1, s2 = nj & 1;
            if (g > wid) continue;
            mma16816b(sacc[nj], qh, bh_[g][s2], bh_[g][s2 + 2]);
            mma16816b(sacc[nj], qh, bl_[g][s2], bl_[g][s2 + 2]);
            mma16816b(sacc[nj], ql, bh_[g][s2], bh_[g][s2 + 2]);
        }
    }

    // causal mask (keep s <= t)
    const int row0 = m0 + r4, row1 = row0 + 8;
#pragma unroll
    for (int nj = 0; nj < 8; nj++) {
        int col = nj * 8 + c2;
        if (col     > row0) sacc[nj][0] = 0.f;
        if (col + 1 > row0) sacc[nj][1] = 0.f;
        if (col     > row1) sacc[nj][2] = 0.f;
        if (col + 1 > row1) sacc[nj][3] = 0.f;
    }

    // S C-frags -> A-frags (hi/lo bf16), only tiles j <= wid (rest are zero)
    uint32_t sh[4][4], sl[4][4];
#pragma unroll
    for (int j = 0; j < 4; j++) {
        if (j > wid) continue;
        split2b(sacc[2 * j][0],     sacc[2 * j][1],     sh[j][0], sl[j][0]);
        split2b(sacc[2 * j][2],     sacc[2 * j][3],     sh[j][1], sl[j][1]);
        split2b(sacc[2 * j + 1][0], sacc[2 * j + 1][1], sh[j][2], sl[j][2]);
        split2b(sacc[2 * j + 1][2], sacc[2 * j + 1][3], sh[j][3], sl[j][3]);
    }

    // ---- gemm2: O = Q @ M^T  (+ gemm3: O += S @ B^T, k-tiles j <= wid) ----
    float oacc[8][4];
#pragma unroll
    for (int j = 0; j < 8; j++)
#pragma unroll
        for (int k = 0; k < 4; k++) oacc[j][k] = 0.f;
#pragma unroll
    for (int t = 0; t < 4; t++) {
        uint32_t qh[4], ql[4], bh_[4][4], bl_[4][4];
        uint32_t aoff = SMEM_SWIZZLE_128B((uint32_t)((m0 + ar) * 128 + t * 32 + ac16 * 16));
        ldsm4(qh, sb + OQ_H + aoff);
        ldsm4(ql, sb + OQ_L + aoff);
#pragma unroll
        for (int g = 0; g < 4; g++) {
            uint32_t boff = SMEM_SWIZZLE_128B((uint32_t)((g * 16 + brow) * 128 + t * 32 + bcsel));
            ldsm4(bh_[g], sb + OM_H + boff);
            ldsm4(bl_[g], sb + OM_L + boff);
        }
#pragma unroll
        for (int nj = 0; nj < 8; nj++) {
            int g = nj >> 1, s2 = nj & 1;
            mma16816b(oacc[nj], qh, bh_[g][s2], bh_[g][s2 + 2]);
            mma16816b(oacc[nj], qh, bl_[g][s2], bl_[g][s2 + 2]);
            mma16816b(oacc[nj], ql, bh_[g][s2], bh_[g][s2 + 2]);
        }
    }
#pragma unroll
    for (int j = 0; j < 4; j++) {              // k-tile over s = 16j..16j+15
        if (j > wid) continue;                 // S[:,s] zero beyond diagonal block
        uint32_t bh_[4][4], bl_[4][4];
#pragma unroll
        for (int g = 0; g < 4; g++) {
            uint32_t boff = SMEM_SWIZZLE_128B((uint32_t)((g * 16 + brow) * 128 + j * 32 + bcsel));
            ldsm4(bh_[g], sb + OB_H + boff);
            ldsm4(bl_[g], sb + OB_L + boff);
        }
#pragma unroll
        for (int nj = 0; nj < 8; nj++) {
            int g = nj >> 1, s2 = nj & 1;
            mma16816b(oacc[nj], sh[j], bh_[g][s2], bh_[g][s2 + 2]);
            mma16816b(oacc[nj], sh[j], bl_[g][s2], bl_[g][s2 + 2]);
            mma16816b(oacc[nj], sl[j], bh_[g][s2], bh_[g][s2 + 2]);
        }
    }

    // epilogue: (o/64) fp32 -> fp16 (rounded once) gmem
#pragma unroll
    for (int nj = 0; nj < 8; nj++) {
        int col = nj * 8 + c2;
        size_t r0o = base + (size_t)row0 * QAB + col;
        size_t r1o = base + (size_t)row1 * QAB + col;
        *reinterpret_cast<uint32_t*>(g_oh + r0o) =
            pack2h(oacc[nj][0] * ISCALE, oacc[nj][1] * ISCALE);
        *reinterpret_cast<uint32_t*>(g_oh + r1o) =
            pack2h(oacc[nj][2] * ISCALE, oacc[nj][3] * ISCALE);
    }
}

// ---------------- launcher: fork/join graph (a-chain overlaps q/b GEMMs) -----
// Streams/events created ONCE on the first call (the correctness run), so they
// are part of the pre-capture memory baseline; nothing is created or destroyed
// during capture, and post-teardown memory returns to baseline. Every call
// issues the identical launch sequence (deterministic work).
static cudaStream_t g_s1 = nullptr, g_s2 = nullptr;
static cudaEvent_t  g_e0 = nullptr, g_e1 = nullptr, g_e2 = nullptr;

extern "C" void kernel_launch(void* const* d_in, const int* in_sizes, int n_in,
                              void* d_out, int out_size) {
    const float* x  = (const float*)d_in[0];
    const float* Wq = (const float*)d_in[1];
    const float* Wa = (const float*)d_in[2];
    const float* Wb = (const float*)d_in[3];
    const float* Wo = (const float*)d_in[4];
    const float* qg = (const float*)d_in[5];
    const float* qb = (const float*)d_in[6];
    const float* ag = (const float*)d_in[7];
    const float* ab = (const float*)d_in[8];
    const float* bg = (const float*)d_in[9];
    const float* bbv = (const float*)d_in[10];
    float* out = (float*)d_out;

    if (!g_s1) {
        cudaStreamCreateWithFlags(&g_s1, cudaStreamNonBlocking);
        cudaStreamCreateWithFlags(&g_s2, cudaStreamNonBlocking);
        cudaEventCreateWithFlags(&g_e0, cudaEventDisableTiming);
        cudaEventCreateWithFlags(&g_e1, cudaEventDisableTiming);
        cudaEventCreateWithFlags(&g_e2, cudaEventDisableTiming);
        cudaFuncSetAttribute(proj_w_kernel, cudaFuncAttributeMaxDynamicSharedMemorySize, GM_SMEM_1);
        cudaFuncSetAttribute(out_tc_kernel, cudaFuncAttributeMaxDynamicSharedMemorySize, GM_SMEM_1);
        cudaFuncSetAttribute(attn_kernel,   cudaFuncAttributeMaxDynamicSharedMemorySize, ATT_SMEM);
    }

    // prologue on origin stream
    split_kernel<<<4096, 256>>>(x);
    wsplit2_kernel<<<dim3(32, 32, 2), 256>>>(Wq, Wa, 0);
    wsplit2_kernel<<<dim3(32, 32, 2), 256>>>(Wb, Wo, 2);
    cudaEventRecord(g_e0, 0);

    // fork
    cudaStreamWaitEvent(g_s1, g_e0, 0);
    cudaStreamWaitEvent(g_s2, g_e0, 0);

    // s1: q and b projections
    proj_w_kernel<<<dim3(8, 32), 256, GM_SMEM_1, g_s1>>>(0, qg, qb);
    proj_w_kernel<<<dim3(8, 32), 256, GM_SMEM_1, g_s1>>>(2, bg, bbv);
    cudaEventRecord(g_e1, g_s1);

    // s2: a projection + cumsum chain (hides under s1's GEMMs)
    proj_w_kernel<<<dim3(8, 32), 256, GM_SMEM_1, g_s2>>>(1, ag, ab);
    chunksum_kernel<<<(Bb * QAB * NC) / 256, 256, 0, g_s2>>>();
    excl_kernel<<<(Bb * QAB * NC) / 256, 256, 0, g_s2>>>();

    // join: chunkP needs g_b (s1) + g_aex (s2)
    cudaStreamWaitEvent(g_s2, g_e1, 0);
    chunkP_kernel<<<Bb * Hh * NC, 256, 0, g_s2>>>();
    scanM_kernel<<<(Bb * Hh * 4096) / 256, 256, 0, g_s2>>>();
    attn_kernel<<<Bb * Hh * NC, 128, ATT_SMEM, g_s2>>>();
    out_tc_kernel<<<dim3(8, 32), 256, GM_SMEM_1, g_s2>>>(out);
    cudaEventRecord(g_e2, g_s2);

    // join back to origin
    cudaStreamWaitEvent(0, g_e2, 0);
}